// round 14
// baseline (speedup 1.0000x reference)
#include <cuda_runtime.h>
#include <cuda_fp16.h>
#include <math.h>
#include <stdint.h>

typedef __half f16;

// ---------------- problem constants ----------------
#define L_   6
#define D_   768
#define NH_  12
#define DH_  64
#define T_   512
#define B_   16
#define BT_  (B_ * T_)       // 8192
#define D3_  (3 * D_)        // 2304
#define D4_  (4 * D_)        // 3072

// ---------------- scratch ----------------
__device__ __align__(128) float g_x  [BT_ * D_];
__device__ __align__(128) float g_xn [BT_ * D_];
__device__ __align__(128) f16   g_qkv[BT_ * D3_];
__device__ __align__(128) f16   g_xh [BT_ * D_];
__device__ __align__(128) f16   g_yh [BT_ * D_];
__device__ __align__(128) f16   g_hh [BT_ * D4_];
__device__ __align__(128) float g_dm [B_ * D_];
__device__ char  g_mask[B_ * T_];
__device__ int   g_lastidx[B_];

__device__ __align__(128) f16 g_qkvT [L_ * D3_ * D_];
__device__ __align__(128) f16 g_projT[L_ * D_ * D_];
__device__ __align__(128) f16 g_fc1T [L_ * D4_ * D_];
__device__ __align__(128) f16 g_fc2T [L_ * D_ * D4_];

// ---------------- PTX helpers ----------------
__device__ __forceinline__ uint32_t smem_u32(const void* p) {
    uint32_t a;
    asm("{ .reg .u64 t; cvta.to.shared.u64 t, %1; cvt.u32.u64 %0, t; }" : "=r"(a) : "l"(p));
    return a;
}
__device__ __forceinline__ void cp16(uint32_t s, const void* g) {
    asm volatile("cp.async.cg.shared.global [%0], [%1], 16;" :: "r"(s), "l"(g) : "memory");
}
__device__ __forceinline__ void ldsm4(uint32_t* r, uint32_t addr) {
    asm volatile("ldmatrix.sync.aligned.m8n8.x4.shared.b16 {%0,%1,%2,%3}, [%4];"
                 : "=r"(r[0]), "=r"(r[1]), "=r"(r[2]), "=r"(r[3]) : "r"(addr));
}
__device__ __forceinline__ void mma16816(float* c, const uint32_t* a, const uint32_t* b) {
    asm volatile(
        "mma.sync.aligned.m16n8k16.row.col.f32.f16.f16.f32 "
        "{%0,%1,%2,%3}, {%4,%5,%6,%7}, {%8,%9}, {%0,%1,%2,%3};"
        : "+f"(c[0]), "+f"(c[1]), "+f"(c[2]), "+f"(c[3])
        : "r"(a[0]), "r"(a[1]), "r"(a[2]), "r"(a[3]), "r"(b[0]), "r"(b[1]));
}
__device__ __forceinline__ float gelu_exact(float v) {
    return 0.5f * v * (1.0f + erff(v * 0.70710678118654752440f));
}
__device__ __forceinline__ uint32_t pack_h2(f16 a, f16 b) {
    __half2 t = __halves2half2(a, b);
    return *(uint32_t*)&t;
}

// ---------------- fused weight transpose + fp16 round ----------------
#define TQKV (L_ * 1728)
#define TPROJ (TQKV + L_ * 576)
#define TFC1 (TPROJ + L_ * 2304)
#define TFC2 (TFC1 + L_ * 2304)

__global__ void transpose_all(const float* __restrict__ qkvw, const float* __restrict__ projw,
                              const float* __restrict__ fc1w, const float* __restrict__ fc2w,
                              f16* __restrict__ qT, f16* __restrict__ pT,
                              f16* __restrict__ f1T, f16* __restrict__ f2T) {
    __shared__ float tile[32][33];
    int idx = blockIdx.x;
    const float* W; f16* Th; int K, N, rem;
    if (idx < TQKV) {
        int layer = idx / 1728; rem = idx % 1728;
        K = D_; N = D3_;
        W = qkvw + (size_t)layer * D_ * D3_;
        Th = qT + (size_t)layer * D3_ * D_;
    } else if (idx < TPROJ) {
        idx -= TQKV;
        int layer = idx / 576; rem = idx % 576;
        K = D_; N = D_;
        W = projw + (size_t)layer * D_ * D_;
        Th = pT + (size_t)layer * D_ * D_;
    } else if (idx < TFC1) {
        idx -= TPROJ;
        int layer = idx / 2304; rem = idx % 2304;
        K = D_; N = D4_;
        W = fc1w + (size_t)layer * D_ * D4_;
        Th = f1T + (size_t)layer * D4_ * D_;
    } else {
        idx -= TFC1;
        int layer = idx / 2304; rem = idx % 2304;
        K = D4_; N = D_;
        W = fc2w + (size_t)layer * D4_ * D_;
        Th = f2T + (size_t)layer * D_ * D4_;
    }
    int tilesN = N >> 5;
    int n0 = (rem % tilesN) << 5;
    int k0 = (rem / tilesN) << 5;
    int tx = threadIdx.x, ty = threadIdx.y;
    #pragma unroll
    for (int i = 0; i < 32; i += 8)
        tile[ty + i][tx] = W[(size_t)(k0 + ty + i) * N + n0 + tx];
    __syncthreads();
    #pragma unroll
    for (int i = 0; i < 32; i += 8) {
        float v = tile[tx][ty + i];
        Th[(size_t)(n0 + ty + i) * K + k0 + tx] = __float2half_rn(v);
    }
}

// ---------------- mask + last_idx ----------------
__global__ void mask_kernel(const int* __restrict__ cards,
                            char* __restrict__ mask, int* __restrict__ lastidx) {
    int b = blockIdx.x;
    int t = threadIdx.x;
    bool valid = cards[b * T_ + t] != 0;
    bool any = __syncthreads_or(valid);
    bool m = valid || (t == 0 && !any);
    mask[b * T_ + t] = m ? 1 : 0;
    int cnt = __syncthreads_count(m);
    if (t == 0) lastidx[b] = (cnt - 1) > 0 ? (cnt - 1) : 0;
}

// ---------------- deck means ----------------
__global__ void deckmean_kernel(const int* __restrict__ deck, const int* __restrict__ opp,
                                const float* __restrict__ tok, float* __restrict__ dm) {
    int b = blockIdx.x;
    int d = threadIdx.x;
    float s = 0.f;
    #pragma unroll
    for (int i = 0; i < 8; i++) {
        s += tok[(size_t)deck[b * 8 + i] * D_ + d];
        s += tok[(size_t)opp [b * 8 + i] * D_ + d];
    }
    dm[b * D_ + d] = s * 0.125f;
}

// ---------------- embedding sum ----------------
__global__ void embed_kernel(const int* __restrict__ cards, const int* __restrict__ players,
                             const float* __restrict__ tok, const float* __restrict__ pemb,
                             const float* __restrict__ pos, const float* __restrict__ dm,
                             float* __restrict__ x) {
    int bt = blockIdx.x;
    int b = bt >> 9;
    int t = bt & 511;
    int card = cards[bt];
    int pl = players[bt]; pl = pl < 0 ? 0 : (pl > 1 ? 1 : pl);
    const float* tr = tok  + (size_t)card * D_;
    const float* pr = pemb + (size_t)pl * D_;
    const float* qr = pos  + (size_t)t * D_;
    const float* mr = dm   + (size_t)b * D_;
    float* xr = x + (size_t)bt * D_;
    for (int d = threadIdx.x; d < D_; d += 256)
        xr[d] = tr[d] + pr[d] + mr[d] + qr[d];
}

// ---------------- layernorm (float4), 256 thr / row, 192 active loaders ------------
template<bool TOH>
__global__ void ln_kernel(const float* __restrict__ x, const float* __restrict__ g,
                          const float* __restrict__ be, float* __restrict__ of,
                          f16* __restrict__ oh) {
    __shared__ float sh1[8], sh2[8];
    int r = blockIdx.x;
    size_t base = (size_t)r * D_;
    int t = threadIdx.x;
    float4 v = make_float4(0.f, 0.f, 0.f, 0.f);
    if (t < 192) v = *(const float4*)(x + base + 4 * t);
    float s = v.x + v.y + v.z + v.w;
    float q = v.x * v.x + v.y * v.y + v.z * v.z + v.w * v.w;
    #pragma unroll
    for (int o2 = 16; o2; o2 >>= 1) {
        s += __shfl_xor_sync(0xffffffffu, s, o2);
        q += __shfl_xor_sync(0xffffffffu, q, o2);
    }
    if ((t & 31) == 0) { sh1[t >> 5] = s; sh2[t >> 5] = q; }
    __syncthreads();
    s = sh1[t & 7]; q = sh2[t & 7];
    #pragma unroll
    for (int o2 = 4; o2; o2 >>= 1) {
        s += __shfl_xor_sync(0xffffffffu, s, o2);
        q += __shfl_xor_sync(0xffffffffu, q, o2);
    }
    float mean = s * (1.0f / D_);
    float var  = q * (1.0f / D_) - mean * mean;
    float rstd = rsqrtf(var + 1e-5f);
    if (t < 192) {
        int d = 4 * t;
        float4 gv = *(const float4*)(g + d);
        float4 bv = *(const float4*)(be + d);
        float o0 = (v.x - mean) * rstd * gv.x + bv.x;
        float o1 = (v.y - mean) * rstd * gv.y + bv.y;
        float o2_ = (v.z - mean) * rstd * gv.z + bv.z;
        float o3 = (v.w - mean) * rstd * gv.w + bv.w;
        if (TOH) {
            __half2 h0 = __halves2half2(__float2half_rn(o0), __float2half_rn(o1));
            __half2 h1 = __halves2half2(__float2half_rn(o2_), __float2half_rn(o3));
            uint2 pk; pk.x = *(uint32_t*)&h0; pk.y = *(uint32_t*)&h1;
            *(uint2*)(oh + base + d) = pk;
        } else {
            *(float4*)(of + base + d) = make_float4(o0, o1, o2_, o3);
        }
    }
}

// ---------------- mma.sync fp16 GEMM, 128xBN tiles, BK=64, 4-stage ring, 1 sync/kt --
// EPI: 0 = bias -> f16; 1 = bias+gelu -> f16; 2 = bias+residual -> fp32
#define ROWB 144                      // 128B data + 16B pad (conflict-free: 144r mod 128 = 16r)
template<int BN> struct GCfg {
    static constexpr int A_OFF = 0;
    static constexpr int B_OFF = 128 * ROWB;
    static constexpr int STAGE = (128 + BN) * ROWB;
    static constexpr int SMEM  = 4 * STAGE;          // BN=256: 221184 B; BN=128: 147456 B
    static constexpr int NF    = BN / 32;
    static constexpr int NPW   = BN / 4;
};

template<int EPI, int BN>
__global__ __launch_bounds__(256, 1)
void gemm_mma(const f16* __restrict__ Ah, const f16* __restrict__ Bh,
              const float* __restrict__ bias, const float* __restrict__ res,
              float* __restrict__ outf, f16* __restrict__ outh,
              int K, int Nfull) {
    using C = GCfg<BN>;
    extern __shared__ char dsm[];
    uint32_t tiles = smem_u32(dsm);

    int tid = threadIdx.x;
    int wid = tid >> 5;
    int lane = tid & 31;
    int warp_m = wid & 1;
    int warp_n = wid >> 1;
    int m0 = blockIdx.y * 128;
    int n0 = blockIdx.x * BN;
    int nt = K >> 6;                   // BK = 64

    int aRow  = lane & 15;
    int aColB = (lane >> 4) << 4;
    int bRow  = (lane & 7) + ((lane & 16) >> 1);
    int bColB = (lane & 8) << 1;

    float acc[4][C::NF][4];
    #pragma unroll
    for (int mt = 0; mt < 4; mt++)
        #pragma unroll
        for (int ntl = 0; ntl < C::NF; ntl++)
            #pragma unroll
            for (int r = 0; r < 4; r++) acc[mt][ntl][r] = 0.f;

    // per stage: A = 128 rows x 128B, B = BN rows x 128B (each thread: 64B halves)
    auto load_stage = [&](int kt, int st) {
        uint32_t sb = tiles + st * C::STAGE;
        int k0 = kt << 6;
        {
            int r = tid >> 1, c = tid & 1;
            size_t go = (size_t)(m0 + r) * K + k0 + (c << 5);
            uint32_t so = sb + C::A_OFF + r * ROWB + (c << 6);
            cp16(so,      Ah + go);
            cp16(so + 16, Ah + go + 8);
            cp16(so + 32, Ah + go + 16);
            cp16(so + 48, Ah + go + 24);
        }
        #pragma unroll
        for (int i = 0; i < BN / 128; i++) {
            int id = tid + (i << 8);
            int r = id >> 1, c = id & 1;
            size_t go = (size_t)(n0 + r) * K + k0 + (c << 5);
            uint32_t so = sb + C::B_OFF + r * ROWB + (c << 6);
            cp16(so,      Bh + go);
            cp16(so + 16, Bh + go + 8);
            cp16(so + 32, Bh + go + 16);
            cp16(so + 48, Bh + go + 24);
        }
        asm volatile("cp.async.commit_group;" ::: "memory");
    };

    load_stage(0, 0);
    load_stage(1, 1);

    uint32_t aH[16], bH[2 * C::NF];

    for (int kt = 0; kt < nt; kt++) {
        int cur = kt & 3;
        if (kt + 2 < nt) {
            load_stage(kt + 2, (kt + 2) & 3);
            asm volatile("cp.async.wait_group 2;" ::: "memory");
        } else if (kt + 1 < nt) {
            asm volatile("cp.async.wait_group 1;" ::: "memory");
        } else {
            asm volatile("cp.async.wait_group 0;" ::: "memory");
        }
        __syncthreads();

        uint32_t sb = tiles + cur * C::STAGE;
        uint32_t aBase = sb + (warp_m * 64 + aRow) * ROWB + aColB;
        uint32_t bBase = sb + C::B_OFF + (warp_n * C::NPW + bRow) * ROWB + bColB;

        #pragma unroll
        for (int ks = 0; ks < 4; ks++) {           // 4 k16 chunks per 64-K stage
            uint32_t kb = ks << 5;
            #pragma unroll
            for (int mt = 0; mt < 4; mt++)
                ldsm4(&aH[4 * mt], aBase + mt * (16 * ROWB) + kb);
            #pragma unroll
            for (int p = 0; p < BN / 64; p++)
                ldsm4(&bH[4 * p], bBase + p * (16 * ROWB) + kb);
            #pragma unroll
            for (int mt = 0; mt < 4; mt++)
                #pragma unroll
                for (int ntl = 0; ntl < C::NF; ntl++)
                    mma16816(acc[mt][ntl], &aH[4 * mt], &bH[2 * ntl]);
        }
    }

    int m_base = m0 + warp_m * 64 + (lane >> 2);
    int n_base = n0 + warp_n * C::NPW + ((lane & 3) << 1);
    #pragma unroll
    for (int mt = 0; mt < 4; mt++) {
        #pragma unroll
        for (int ntl = 0; ntl < C::NF; ntl++) {
            int n = n_base + ntl * 8;
            float b0 = bias[n], b1 = bias[n + 1];
            #pragma unroll
            for (int rr = 0; rr < 2; rr++) {
                int m = m_base + mt * 16 + rr * 8;
                size_t ob = (size_t)m * Nfull + n;
                float v0 = acc[mt][ntl][2 * rr]     + b0;
                float v1 = acc[mt][ntl][2 * rr + 1] + b1;
                if (EPI == 0) {
                    *(__half2*)(outh + ob) =
                        __halves2half2(__float2half_rn(v0), __float2half_rn(v1));
                } else if (EPI == 2) {
                    float2 rv = *(const float2*)(res + ob);
                    *(float2*)(outf + ob) = make_float2(v0 + rv.x, v1 + rv.y);
                } else {
                    float g0 = gelu_exact(v0), g1 = gelu_exact(v1);
                    *(__half2*)(outh + ob) =
                        __halves2half2(__float2half_rn(g0), __float2half_rn(g1));
                }
            }
        }
    }
}

// ---------------- tensor-core flash attention (fp16 qkv in, fp32 softmax) ----------
#define QSTR 72
#define VSTR 40

__global__ __launch_bounds__(128)
void attn_kernel(const f16* __restrict__ qkv, const char* __restrict__ mask,
                 f16* __restrict__ outh) {
    __shared__ f16 sQ[64 * QSTR];
    __shared__ f16 sK[32 * QSTR];
    __shared__ f16 sV[64 * VSTR];    // V^T: [dim][key]
    __shared__ char Ms[32];

    int qt = blockIdx.x, h = blockIdx.y, b = blockIdx.z;
    int tid = threadIdx.x;
    int wid = tid >> 5, lane = tid & 31;
    int grp = lane >> 2, qd = lane & 3;

    {
        int row = tid >> 1;
        int c0 = (tid & 1) * 32;
        const f16* g = qkv + ((size_t)(b * T_ + qt * 64 + row)) * D3_ + h * DH_ + c0;
        __half2 sc = __half2half2(__float2half(0.125f));
        #pragma unroll
        for (int u = 0; u < 16; u++) {
            __half2 v = *(const __half2*)(g + 2 * u);
            *(__half2*)&sQ[row * QSTR + c0 + 2 * u] = __hmul2(v, sc);
        }
    }

    float O[8][4];
    #pragma unroll
    for (int nf = 0; nf < 8; nf++)
        #pragma unroll
        for (int r = 0; r < 4; r++) O[nf][r] = 0.f;
    float m_a = -INFINITY, m_b = -INFINITY, l_a = 0.f, l_b = 0.f;

    uint32_t aAddr = smem_u32(sQ) + (wid * 16 + (lane & 15)) * (QSTR * 2) + ((lane >> 4) << 4);
    int bRow  = (lane & 7) + ((lane & 16) >> 1);
    int bColB = (lane & 8) << 1;
    uint32_t kAddr = smem_u32(sK) + bRow * (QSTR * 2) + bColB;
    uint32_t vAddr = smem_u32(sV) + bRow * (VSTR * 2) + bColB;

    int q_a = qt * 64 + wid * 16 + grp;
    int q_b = q_a + 8;

    int ktmax = (qt + 1) * 2;
    for (int kt = 0; kt < ktmax; kt++) {
        __syncthreads();
        {
            int j  = tid >> 2;
            int d0 = (tid & 3) * 16;
            const f16* gk = qkv + ((size_t)(b * T_ + kt * 32 + j)) * D3_ + D_ + h * DH_ + d0;
            const f16* gv = gk + D_;
            #pragma unroll
            for (int u = 0; u < 2; u++)
                *(uint4*)&sK[j * QSTR + d0 + u * 8] = *(const uint4*)(gk + u * 8);
            #pragma unroll
            for (int u = 0; u < 8; u++) {
                __half2 v = *(const __half2*)(gv + 2 * u);
                int d = d0 + 2 * u;
                sV[(d + 0) * VSTR + j] = __low2half(v);
                sV[(d + 1) * VSTR + j] = __high2half(v);
            }
            if (tid < 32) Ms[tid] = mask[b * T_ + kt * 32 + tid];
        }
        __syncthreads();

        float S[4][4];
        #pragma unroll
        for (int f = 0; f < 4; f++)
            #pragma unroll
            for (int r = 0; r < 4; r++) S[f][r] = 0.f;
        #pragma unroll
        for (int kc = 0; kc < 4; kc++) {
            uint32_t q[4], kf[8];
            ldsm4(q, aAddr + kc * 32);
            ldsm4(&kf[0], kAddr + kc * 32);
            ldsm4(&kf[4], kAddr + 16 * (QSTR * 2) + kc * 32);
            #pragma unroll
            for (int f = 0; f < 4; f++)
                mma16816(S[f], q, &kf[2 * f]);
        }

        float mt_a = -INFINITY, mt_b = -INFINITY;
        #pragma unroll
        for (int f = 0; f < 4; f++) {
            int ci = f * 8 + qd * 2;
            int gk0 = kt * 32 + ci, gk1 = gk0 + 1;
            bool ok0 = Ms[ci] != 0, ok1 = Ms[ci + 1] != 0;
            S[f][0] = (ok0 && gk0 <= q_a) ? S[f][0] : -INFINITY;
            S[f][1] = (ok1 && gk1 <= q_a) ? S[f][1] : -INFINITY;
            S[f][2] = (ok0 && gk0 <= q_b) ? S[f][2] : -INFINITY;
            S[f][3] = (ok1 && gk1 <= q_b) ? S[f][3] : -INFINITY;
            mt_a = fmaxf(mt_a, fmaxf(S[f][0], S[f][1]));
            mt_b = fmaxf(mt_b, fmaxf(S[f][2], S[f][3]));
        }
        mt_a = fmaxf(mt_a, __shfl_xor_sync(0xffffffffu, mt_a, 1));
        mt_a = fmaxf(mt_a, __shfl_xor_sync(0xffffffffu, mt_a, 2));
        mt_b = fmaxf(mt_b, __shfl_xor_sync(0xffffffffu, mt_b, 1));
        mt_b = fmaxf(mt_b, __shfl_xor_sync(0xffffffffu, mt_b, 2));
        float mn_a = fmaxf(m_a, mt_a), mn_b = fmaxf(m_b, mt_b);
        float al_a, al_b, ps_a = 0.f, ps_b = 0.f;
        if (mn_a == -INFINITY) {
            al_a = 1.f;
            #pragma unroll
            for (int f = 0; f < 4; f++) { S[f][0] = 0.f; S[f][1] = 0.f; }
        } else {
            al_a = expf(m_a - mn_a);
            #pragma unroll
            for (int f = 0; f < 4; f++) {
                S[f][0] = expf(S[f][0] - mn_a);
                S[f][1] = expf(S[f][1] - mn_a);
                ps_a += S[f][0] + S[f][1];
            }
        }
        if (mn_b == -INFINITY) {
            al_b = 1.f;
            #pragma unroll
            for (int f = 0; f < 4; f++) { S[f][2] = 0.f; S[f][3] = 0.f; }
        } else {
            al_b = expf(m_b - mn_b);
            #pragma unroll
            for (int f = 0; f < 4; f++) {
                S[f][2] = expf(S[f][2] - mn_b);
                S[f][3] = expf(S[f][3] - mn_b);
                ps_b += S[f][2] + S[f][3];
            }
        }
        ps_a += __shfl_xor_sync(0xffffffffu, ps_a, 1);
        ps_a += __shfl_xor_sync(0xffffffffu, ps_a, 2);
        ps_b += __shfl_xor_sync(0xffffffffu, ps_b, 1);
        ps_b += __shfl_xor_sync(0xffffffffu, ps_b, 2);
        l_a = l_a * al_a + ps_a;
        l_b = l_b * al_b + ps_b;
        m_a = mn_a; m_b = mn_b;
        #pragma unroll
        for (int nf = 0; nf < 8; nf++) {
            O[nf][0] *= al_a; O[nf][1] *= al_a;
            O[nf][2] *= al_b; O[nf][3] *= al_b;
        }

        #pragma unroll
        for (int kc = 0; kc < 2; kc++) {
            int f0 = 2 * kc, f1 = 2 * kc + 1;
            uint32_t pa[4];
            pa[0] = pack_h2(__float2half_rn(S[f0][0]), __float2half_rn(S[f0][1]));
            pa[1] = pack_h2(__float2half_rn(S[f0][2]), __float2half_rn(S[f0][3]));
            pa[2] = pack_h2(__float2half_rn(S[f1][0]), __float2half_rn(S[f1][1]));
            pa[3] = pack_h2(__float2half_rn(S[f1][2]), __float2half_rn(S[f1][3]));
            uint32_t vf[16];
            #pragma unroll
            for (int p4 = 0; p4 < 4; p4++)
                ldsm4(&vf[4 * p4], vAddr + p4 * 16 * (VSTR * 2) + kc * 32);
            #pragma unroll
            for (int nf = 0; nf < 8; nf++)
                mma16816(O[nf], pa, &vf[2 * nf]);
        }
    }

    float rl_a = (l_a > 0.f) ? (1.f / l_a) : 0.f;
    float rl_b = (l_b > 0.f) ? (1.f / l_b) : 0.f;
    size_t rowA = (size_t)(b * T_) + qt * 64 + wid * 16 + grp;
    size_t rowB = rowA + 8;
    #pragma unroll
    for (int nf = 0; nf < 8; nf++) {
        int col = h * DH_ + nf * 8 + qd * 2;
        *(__half2*)(outh + rowA * D_ + col) = __halves2half2(
            __float2half_rn(O[nf][0] * rl_a), __float2half_rn(O[nf][1] * rl_a));
        *(__half2*)(outh + rowB * D_ + col) = __halves2half2(
            __float2half_rn(O[nf][2] * rl_b), __float2half_rn(O[nf][3] * rl_b));
    }
}

// ---------------- head ----------------
__global__ void head_kernel(const float* __restrict__ xn, const int* __restrict__ lastidx,
                            const float* __restrict__ hw, const float* __restrict__ hb,
                            float* __restrict__ out) {
    int b = blockIdx.x;
    int w = threadIdx.x >> 5;
    int lane = threadIdx.x & 31;
    const float* h = xn + ((size_t)(b * T_ + lastidx[b])) * D_;
    float s = 0.f;
    for (int d = lane; d < D_; d += 32) s += h[d] * hw[d * 9 + w];
    #pragma unroll
    for (int o = 16; o; o >>= 1) s += __shfl_down_sync(0xffffffffu, s, o);
    if (lane == 0) out[b * 9 + w] = s + hb[w];
}

// ---------------- orchestration ----------------
extern "C" void kernel_launch(void* const* d_in, const int* in_sizes, int n_in,
                              void* d_out, int out_size) {
    const int*   cards   = (const int*)  d_in[0];
    const int*   players = (const int*)  d_in[1];
    const int*   deck    = (const int*)  d_in[2];
    const int*   opp     = (const int*)  d_in[3];
    const float* tok     = (const float*)d_in[4];
    const float* pemb    = (const float*)d_in[5];
    const float* pos     = (const float*)d_in[6];
    const float* ln1s = (const float*)d_in[9];
    const float* ln1b = (const float*)d_in[10];
    const float* qkvw = (const float*)d_in[11];
    const float* qkvb = (const float*)d_in[12];
    const float* projw = (const float*)d_in[13];
    const float* projb = (const float*)d_in[14];
    const float* ln2s = (const float*)d_in[15];
    const float* ln2b = (const float*)d_in[16];
    const float* fc1w = (const float*)d_in[17];
    const float* fc1b = (const float*)d_in[18];
    const float* fc2w = (const float*)d_in[19];
    const float* fc2b = (const float*)d_in[20];
    const float* lnfs = (const float*)d_in[21];
    const float* lnfb = (const float*)d_in[22];
    const float* headw = (const float*)d_in[23];
    const float* headb = (const float*)d_in[24];

    float *x, *xn, *dm;
    f16 *qkv, *xh, *yh, *hh;
    f16 *qT, *pT, *f1T, *f2T;
    char* mask; int* lastidx;
    cudaGetSymbolAddress((void**)&x,    g_x);
    cudaGetSymbolAddress((void**)&xn,   g_xn);
    cudaGetSymbolAddress((void**)&qkv,  g_qkv);
    cudaGetSymbolAddress((void**)&dm,   g_dm);
    cudaGetSymbolAddress((void**)&xh,   g_xh);
    cudaGetSymbolAddress((void**)&yh,   g_yh);
    cudaGetSymbolAddress((void**)&hh,   g_hh);
    cudaGetSymbolAddress((void**)&qT,   g_qkvT);
    cudaGetSymbolAddress((void**)&pT,   g_projT);
    cudaGetSymbolAddress((void**)&f1T,  g_fc1T);
    cudaGetSymbolAddress((void**)&f2T,  g_fc2T);
    cudaGetSymbolAddress((void**)&mask, g_mask);
    cudaGetSymbolAddress((void**)&lastidx, g_lastidx);

    cudaFuncSetAttribute((const void*)gemm_mma<0, 256>,
                         cudaFuncAttributeMaxDynamicSharedMemorySize, GCfg<256>::SMEM);
    cudaFuncSetAttribute((const void*)gemm_mma<1, 128>,
                         cudaFuncAttributeMaxDynamicSharedMemorySize, GCfg<128>::SMEM);
    cudaFuncSetAttribute((const void*)gemm_mma<2, 128>,
                         cudaFuncAttributeMaxDynamicSharedMemorySize, GCfg<128>::SMEM);

    dim3 tb(32, 8);
    transpose_all<<<TFC2, tb>>>(qkvw, projw, fc1w, fc2w, qT, pT, f1T, f2T);
    mask_kernel<<<B_, T_>>>(cards, mask, lastidx);
    deckmean_kernel<<<B_, D_>>>(deck, opp, tok, dm);
    embed_kernel<<<BT_, 256>>>(cards, players, tok, pemb, pos, dm, x);

    for (int i = 0; i < L_; i++) {
        ln_kernel<true><<<BT_, 256>>>(x, ln1s + i * D_, ln1b + i * D_, nullptr, xh);
        gemm_mma<0, 256><<<dim3(D3_ / 256, BT_ / 128), 256, GCfg<256>::SMEM>>>(
            xh, qT + (size_t)i * D3_ * D_,
            qkvb + i * D3_, nullptr, nullptr, qkv, D_, D3_);
        attn_kernel<<<dim3(T_ / 64, NH_, B_), 128>>>(qkv, mask, yh);
        gemm_mma<2, 128><<<dim3(D_ / 128, BT_ / 128), 256, GCfg<128>::SMEM>>>(
            yh, pT + (size_t)i * D_ * D_,
            projb + i * D_, x, x, nullptr, D_, D_);
        ln_kernel<true><<<BT_, 256>>>(x, ln2s + i * D_, ln2b + i * D_, nullptr, xh);
        gemm_mma<1, 128><<<dim3(D4_ / 128, BT_ / 128), 256, GCfg<128>::SMEM>>>(
            xh, f1T + (size_t)i * D4_ * D_,
            fc1b + i * D4_, nullptr, nullptr, hh, D_, D4_);
        gemm_mma<2, 128><<<dim3(D_ / 128, BT_ / 128), 256, GCfg<128>::SMEM>>>(
            hh, f2T + (size_t)i * D_ * D4_,
            fc2b + i * D_, x, x, nullptr, D4_, D_);
    }

    ln_kernel<false><<<BT_, 256>>>(x, lnfs, lnfb, xn, nullptr);
    head_kernel<<<B_, 288>>>(xn, lastidx, headw, headb, (float*)d_out);
}

// round 15
// speedup vs baseline: 1.1847x; 1.1847x over previous
#include <cuda_runtime.h>
#include <cuda_fp16.h>
#include <math.h>
#include <stdint.h>

typedef __half f16;

// ---------------- problem constants ----------------
#define L_   6
#define D_   768
#define NH_  12
#define DH_  64
#define T_   512
#define B_   16
#define BT_  (B_ * T_)       // 8192
#define D3_  (3 * D_)        // 2304
#define D4_  (4 * D_)        // 3072

// ---------------- scratch ----------------
__device__ __align__(128) float g_x  [BT_ * D_];
__device__ __align__(128) float g_xn [BT_ * D_];
__device__ __align__(128) f16   g_qkv[BT_ * D3_];
__device__ __align__(128) f16   g_xh [BT_ * D_];
__device__ __align__(128) f16   g_yh [BT_ * D_];
__device__ __align__(128) f16   g_hh [BT_ * D4_];
__device__ __align__(128) float g_dm [B_ * D_];
__device__ char  g_mask[B_ * T_];
__device__ int   g_lastidx[B_];

__device__ __align__(128) f16 g_qkvT [L_ * D3_ * D_];
__device__ __align__(128) f16 g_projT[L_ * D_ * D_];
__device__ __align__(128) f16 g_fc1T [L_ * D4_ * D_];
__device__ __align__(128) f16 g_fc2T [L_ * D_ * D4_];

// ---------------- PTX helpers ----------------
__device__ __forceinline__ uint32_t smem_u32(const void* p) {
    uint32_t a;
    asm("{ .reg .u64 t; cvta.to.shared.u64 t, %1; cvt.u32.u64 %0, t; }" : "=r"(a) : "l"(p));
    return a;
}
__device__ __forceinline__ void cp16(uint32_t s, const void* g) {
    asm volatile("cp.async.cg.shared.global [%0], [%1], 16;" :: "r"(s), "l"(g) : "memory");
}
__device__ __forceinline__ void ldsm4(uint32_t* r, uint32_t addr) {
    asm volatile("ldmatrix.sync.aligned.m8n8.x4.shared.b16 {%0,%1,%2,%3}, [%4];"
                 : "=r"(r[0]), "=r"(r[1]), "=r"(r[2]), "=r"(r[3]) : "r"(addr));
}
__device__ __forceinline__ void mma16816(float* c, const uint32_t* a, const uint32_t* b) {
    asm volatile(
        "mma.sync.aligned.m16n8k16.row.col.f32.f16.f16.f32 "
        "{%0,%1,%2,%3}, {%4,%5,%6,%7}, {%8,%9}, {%0,%1,%2,%3};"
        : "+f"(c[0]), "+f"(c[1]), "+f"(c[2]), "+f"(c[3])
        : "r"(a[0]), "r"(a[1]), "r"(a[2]), "r"(a[3]), "r"(b[0]), "r"(b[1]));
}
__device__ __forceinline__ float gelu_exact(float v) {
    return 0.5f * v * (1.0f + erff(v * 0.70710678118654752440f));
}
__device__ __forceinline__ uint32_t pack_h2(f16 a, f16 b) {
    __half2 t = __halves2half2(a, b);
    return *(uint32_t*)&t;
}

// ---------------- fused weight transpose + fp16 round ----------------
#define TQKV (L_ * 1728)
#define TPROJ (TQKV + L_ * 576)
#define TFC1 (TPROJ + L_ * 2304)
#define TFC2 (TFC1 + L_ * 2304)

__global__ void transpose_all(const float* __restrict__ qkvw, const float* __restrict__ projw,
                              const float* __restrict__ fc1w, const float* __restrict__ fc2w,
                              f16* __restrict__ qT, f16* __restrict__ pT,
                              f16* __restrict__ f1T, f16* __restrict__ f2T) {
    __shared__ float tile[32][33];
    int idx = blockIdx.x;
    const float* W; f16* Th; int K, N, rem;
    if (idx < TQKV) {
        int layer = idx / 1728; rem = idx % 1728;
        K = D_; N = D3_;
        W = qkvw + (size_t)layer * D_ * D3_;
        Th = qT + (size_t)layer * D3_ * D_;
    } else if (idx < TPROJ) {
        idx -= TQKV;
        int layer = idx / 576; rem = idx % 576;
        K = D_; N = D_;
        W = projw + (size_t)layer * D_ * D_;
        Th = pT + (size_t)layer * D_ * D_;
    } else if (idx < TFC1) {
        idx -= TPROJ;
        int layer = idx / 2304; rem = idx % 2304;
        K = D_; N = D4_;
        W = fc1w + (size_t)layer * D_ * D4_;
        Th = f1T + (size_t)layer * D4_ * D_;
    } else {
        idx -= TFC1;
        int layer = idx / 2304; rem = idx % 2304;
        K = D4_; N = D_;
        W = fc2w + (size_t)layer * D4_ * D_;
        Th = f2T + (size_t)layer * D_ * D4_;
    }
    int tilesN = N >> 5;
    int n0 = (rem % tilesN) << 5;
    int k0 = (rem / tilesN) << 5;
    int tx = threadIdx.x, ty = threadIdx.y;
    #pragma unroll
    for (int i = 0; i < 32; i += 8)
        tile[ty + i][tx] = W[(size_t)(k0 + ty + i) * N + n0 + tx];
    __syncthreads();
    #pragma unroll
    for (int i = 0; i < 32; i += 8) {
        float v = tile[tx][ty + i];
        Th[(size_t)(n0 + ty + i) * K + k0 + tx] = __float2half_rn(v);
    }
}

// ---------------- mask + last_idx ----------------
__global__ void mask_kernel(const int* __restrict__ cards,
                            char* __restrict__ mask, int* __restrict__ lastidx) {
    int b = blockIdx.x;
    int t = threadIdx.x;
    bool valid = cards[b * T_ + t] != 0;
    bool any = __syncthreads_or(valid);
    bool m = valid || (t == 0 && !any);
    mask[b * T_ + t] = m ? 1 : 0;
    int cnt = __syncthreads_count(m);
    if (t == 0) lastidx[b] = (cnt - 1) > 0 ? (cnt - 1) : 0;
}

// ---------------- deck means ----------------
__global__ void deckmean_kernel(const int* __restrict__ deck, const int* __restrict__ opp,
                                const float* __restrict__ tok, float* __restrict__ dm) {
    int b = blockIdx.x;
    int d = threadIdx.x;
    float s = 0.f;
    #pragma unroll
    for (int i = 0; i < 8; i++) {
        s += tok[(size_t)deck[b * 8 + i] * D_ + d];
        s += tok[(size_t)opp [b * 8 + i] * D_ + d];
    }
    dm[b * D_ + d] = s * 0.125f;
}

// ---------------- embedding sum ----------------
__global__ void embed_kernel(const int* __restrict__ cards, const int* __restrict__ players,
                             const float* __restrict__ tok, const float* __restrict__ pemb,
                             const float* __restrict__ pos, const float* __restrict__ dm,
                             float* __restrict__ x) {
    int bt = blockIdx.x;
    int b = bt >> 9;
    int t = bt & 511;
    int card = cards[bt];
    int pl = players[bt]; pl = pl < 0 ? 0 : (pl > 1 ? 1 : pl);
    const float* tr = tok  + (size_t)card * D_;
    const float* pr = pemb + (size_t)pl * D_;
    const float* qr = pos  + (size_t)t * D_;
    const float* mr = dm   + (size_t)b * D_;
    float* xr = x + (size_t)bt * D_;
    for (int d = threadIdx.x; d < D_; d += 256)
        xr[d] = tr[d] + pr[d] + mr[d] + qr[d];
}

// ---------------- layernorm (float4), 256 thr / row, 192 active loaders ------------
template<bool TOH>
__global__ void ln_kernel(const float* __restrict__ x, const float* __restrict__ g,
                          const float* __restrict__ be, float* __restrict__ of,
                          f16* __restrict__ oh) {
    __shared__ float sh1[8], sh2[8];
    int r = blockIdx.x;
    size_t base = (size_t)r * D_;
    int t = threadIdx.x;
    float4 v = make_float4(0.f, 0.f, 0.f, 0.f);
    if (t < 192) v = *(const float4*)(x + base + 4 * t);
    float s = v.x + v.y + v.z + v.w;
    float q = v.x * v.x + v.y * v.y + v.z * v.z + v.w * v.w;
    #pragma unroll
    for (int o2 = 16; o2; o2 >>= 1) {
        s += __shfl_xor_sync(0xffffffffu, s, o2);
        q += __shfl_xor_sync(0xffffffffu, q, o2);
    }
    if ((t & 31) == 0) { sh1[t >> 5] = s; sh2[t >> 5] = q; }
    __syncthreads();
    s = sh1[t & 7]; q = sh2[t & 7];
    #pragma unroll
    for (int o2 = 4; o2; o2 >>= 1) {
        s += __shfl_xor_sync(0xffffffffu, s, o2);
        q += __shfl_xor_sync(0xffffffffu, q, o2);
    }
    float mean = s * (1.0f / D_);
    float var  = q * (1.0f / D_) - mean * mean;
    float rstd = rsqrtf(var + 1e-5f);
    if (t < 192) {
        int d = 4 * t;
        float4 gv = *(const float4*)(g + d);
        float4 bv = *(const float4*)(be + d);
        float o0 = (v.x - mean) * rstd * gv.x + bv.x;
        float o1 = (v.y - mean) * rstd * gv.y + bv.y;
        float o2_ = (v.z - mean) * rstd * gv.z + bv.z;
        float o3 = (v.w - mean) * rstd * gv.w + bv.w;
        if (TOH) {
            __half2 h0 = __halves2half2(__float2half_rn(o0), __float2half_rn(o1));
            __half2 h1 = __halves2half2(__float2half_rn(o2_), __float2half_rn(o3));
            uint2 pk; pk.x = *(uint32_t*)&h0; pk.y = *(uint32_t*)&h1;
            *(uint2*)(oh + base + d) = pk;
        } else {
            *(float4*)(of + base + d) = make_float4(o0, o1, o2_, o3);
        }
    }
}

// ---------------- mma.sync fp16 GEMM (R13 config: BK=32, 4-stage ring, 1 sync/kt) --
// EPI: 0 = bias -> f16; 1 = bias+gelu -> f16; 2 = bias+residual -> fp32
#define ROWB 80
template<int BN> struct GCfg {
    static constexpr int A_OFF = 0;
    static constexpr int B_OFF = 128 * ROWB;
    static constexpr int STAGE = (128 + BN) * ROWB;
    static constexpr int SMEM  = 4 * STAGE;
    static constexpr int NF    = BN / 32;
    static constexpr int NPW   = BN / 4;
};

template<int EPI, int BN>
__global__ __launch_bounds__(256, 1)
void gemm_mma(const f16* __restrict__ Ah, const f16* __restrict__ Bh,
              const float* __restrict__ bias, const float* __restrict__ res,
              float* __restrict__ outf, f16* __restrict__ outh,
              int K, int Nfull) {
    using C = GCfg<BN>;
    extern __shared__ char dsm[];
    uint32_t tiles = smem_u32(dsm);

    int tid = threadIdx.x;
    int wid = tid >> 5;
    int lane = tid & 31;
    int warp_m = wid & 1;
    int warp_n = wid >> 1;
    int m0 = blockIdx.y * 128;
    int n0 = blockIdx.x * BN;
    int nt = K >> 5;

    int aRow  = lane & 15;
    int aColB = (lane >> 4) << 4;
    int bRow  = (lane & 7) + ((lane & 16) >> 1);
    int bColB = (lane & 8) << 1;

    float acc[4][C::NF][4];
    #pragma unroll
    for (int mt = 0; mt < 4; mt++)
        #pragma unroll
        for (int ntl = 0; ntl < C::NF; ntl++)
            #pragma unroll
            for (int r = 0; r < 4; r++) acc[mt][ntl][r] = 0.f;

    auto load_stage = [&](int kt, int st) {
        uint32_t sb = tiles + st * C::STAGE;
        int k0 = kt << 5;
        #pragma unroll
        for (int i = 0; i < 2; i++) {
            int id = tid + (i << 8);
            int r = id >> 2, c = id & 3;
            size_t go = (size_t)(m0 + r) * K + k0 + (c << 3);
            cp16(sb + C::A_OFF + r * ROWB + (c << 4), Ah + go);
        }
        #pragma unroll
        for (int i = 0; i < BN / 64; i++) {
            int id = tid + (i << 8);
            int r = id >> 2, c = id & 3;
            size_t go = (size_t)(n0 + r) * K + k0 + (c << 3);
            cp16(sb + C::B_OFF + r * ROWB + (c << 4), Bh + go);
        }
        asm volatile("cp.async.commit_group;" ::: "memory");
    };

    load_stage(0, 0);
    load_stage(1, 1);

    uint32_t aH[16], bH[2 * C::NF];

    for (int kt = 0; kt < nt; kt++) {
        int cur = kt & 3;
        if (kt + 2 < nt) {
            load_stage(kt + 2, (kt + 2) & 3);
            asm volatile("cp.async.wait_group 2;" ::: "memory");
        } else if (kt + 1 < nt) {
            asm volatile("cp.async.wait_group 1;" ::: "memory");
        } else {
            asm volatile("cp.async.wait_group 0;" ::: "memory");
        }
        __syncthreads();

        uint32_t sb = tiles + cur * C::STAGE;
        uint32_t aBase = sb + (warp_m * 64 + aRow) * ROWB + aColB;
        uint32_t bBase = sb + C::B_OFF + (warp_n * C::NPW + bRow) * ROWB + bColB;

        #pragma unroll
        for (int ks = 0; ks < 2; ks++) {
            uint32_t kb = ks << 5;
            #pragma unroll
            for (int mt = 0; mt < 4; mt++)
                ldsm4(&aH[4 * mt], aBase + mt * (16 * ROWB) + kb);
            #pragma unroll
            for (int p = 0; p < BN / 64; p++)
                ldsm4(&bH[4 * p], bBase + p * (16 * ROWB) + kb);
            #pragma unroll
            for (int mt = 0; mt < 4; mt++)
                #pragma unroll
                for (int ntl = 0; ntl < C::NF; ntl++)
                    mma16816(acc[mt][ntl], &aH[4 * mt], &bH[2 * ntl]);
        }
    }

    int m_base = m0 + warp_m * 64 + (lane >> 2);
    int n_base = n0 + warp_n * C::NPW + ((lane & 3) << 1);
    #pragma unroll
    for (int mt = 0; mt < 4; mt++) {
        #pragma unroll
        for (int ntl = 0; ntl < C::NF; ntl++) {
            int n = n_base + ntl * 8;
            float b0 = bias[n], b1 = bias[n + 1];
            #pragma unroll
            for (int rr = 0; rr < 2; rr++) {
                int m = m_base + mt * 16 + rr * 8;
                size_t ob = (size_t)m * Nfull + n;
                float v0 = acc[mt][ntl][2 * rr]     + b0;
                float v1 = acc[mt][ntl][2 * rr + 1] + b1;
                if (EPI == 0) {
                    *(__half2*)(outh + ob) =
                        __halves2half2(__float2half_rn(v0), __float2half_rn(v1));
                } else if (EPI == 2) {
                    float2 rv = *(const float2*)(res + ob);
                    *(float2*)(outf + ob) = make_float2(v0 + rv.x, v1 + rv.y);
                } else {
                    float g0 = gelu_exact(v0), g1 = gelu_exact(v1);
                    *(__half2*)(outh + ob) =
                        __halves2half2(__float2half_rn(g0), __float2half_rn(g1));
                }
            }
        }
    }
}

// ---------------- tensor-core flash attention, double-buffered K/V, 1 sync/kt ------
#define QSTR 72
#define VSTR 40
#define KBUF (32 * QSTR)
#define VBUF (64 * VSTR)

__global__ __launch_bounds__(128)
void attn_kernel(const f16* __restrict__ qkv, const char* __restrict__ mask,
                 f16* __restrict__ outh) {
    __shared__ f16 sQ[64 * QSTR];
    __shared__ f16 sK[2 * KBUF];
    __shared__ f16 sV[2 * VBUF];     // V^T: [dim][key]
    __shared__ char Ms[2][32];

    int qt = blockIdx.x, h = blockIdx.y, b = blockIdx.z;
    int tid = threadIdx.x;
    int wid = tid >> 5, lane = tid & 31;
    int grp = lane >> 2, qd = lane & 3;

    // ---- fill helper: K (row copy) + V^T + mask into buffer bi ----
    auto fill = [&](int kt, int bi) {
        int j  = tid >> 2;
        int d0 = (tid & 3) * 16;
        const f16* gk = qkv + ((size_t)(b * T_ + kt * 32 + j)) * D3_ + D_ + h * DH_ + d0;
        const f16* gv = gk + D_;
        f16* dk = sK + bi * KBUF;
        f16* dv = sV + bi * VBUF;
        #pragma unroll
        for (int u = 0; u < 2; u++)
            *(uint4*)&dk[j * QSTR + d0 + u * 8] = *(const uint4*)(gk + u * 8);
        #pragma unroll
        for (int u = 0; u < 8; u++) {
            __half2 v = *(const __half2*)(gv + 2 * u);
            int d = d0 + 2 * u;
            dv[(d + 0) * VSTR + j] = __low2half(v);
            dv[(d + 1) * VSTR + j] = __high2half(v);
        }
        if (tid < 32) Ms[bi][tid] = mask[b * T_ + kt * 32 + tid];
    };

    // ---- load Q (64x64 f16), scale by 1/8 (exact in fp16) ----
    {
        int row = tid >> 1;
        int c0 = (tid & 1) * 32;
        const f16* g = qkv + ((size_t)(b * T_ + qt * 64 + row)) * D3_ + h * DH_ + c0;
        __half2 sc = __half2half2(__float2half(0.125f));
        #pragma unroll
        for (int u = 0; u < 16; u++) {
            __half2 v = *(const __half2*)(g + 2 * u);
            *(__half2*)&sQ[row * QSTR + c0 + 2 * u] = __hmul2(v, sc);
        }
    }
    fill(0, 0);

    float O[8][4];
    #pragma unroll
    for (int nf = 0; nf < 8; nf++)
        #pragma unroll
        for (int r = 0; r < 4; r++) O[nf][r] = 0.f;
    float m_a = -INFINITY, m_b = -INFINITY, l_a = 0.f, l_b = 0.f;

    uint32_t aAddr = smem_u32(sQ) + (wid * 16 + (lane & 15)) * (QSTR * 2) + ((lane >> 4) << 4);
    int bRow  = (lane & 7) + ((lane & 16) >> 1);
    int bColB = (lane & 8) << 1;
    uint32_t kAddr0 = smem_u32(sK) + bRow * (QSTR * 2) + bColB;
    uint32_t vAddr0 = smem_u32(sV) + bRow * (VSTR * 2) + bColB;

    int q_a = qt * 64 + wid * 16 + grp;
    int q_b = q_a + 8;

    int ktmax = (qt + 1) * 2;
    for (int kt = 0; kt < ktmax; kt++) {
        int bi = kt & 1;
        __syncthreads();                   // publishes fill(kt); guards buffer (kt+1)&1 reuse
        if (kt + 1 < ktmax) fill(kt + 1, bi ^ 1);

        uint32_t kAddr = kAddr0 + bi * (KBUF * 2);
        uint32_t vAddr = vAddr0 + bi * (VBUF * 2);

        // ---- S = Q K^T (m16 x n32, k64) ----
        float S[4][4];
        #pragma unroll
        for (int f = 0; f < 4; f++)
            #pragma unroll
            for (int r = 0; r < 4; r++) S[f][r] = 0.f;
        #pragma unroll
        for (int kc = 0; kc < 4; kc++) {
            uint32_t q[4], kf[8];
            ldsm4(q, aAddr + kc * 32);
            ldsm4(&kf[0], kAddr + kc * 32);
            ldsm4(&kf[4], kAddr + 16 * (QSTR * 2) + kc * 32);
            #pragma unroll
            for (int f = 0; f < 4; f++)
                mma16816(S[f], q, &kf[2 * f]);
        }

        // ---- mask + online softmax ----
        float mt_a = -INFINITY, mt_b = -INFINITY;
        #pragma unroll
        for (int f = 0; f < 4; f++) {
            int ci = f * 8 + qd * 2;
            int gk0 = kt * 32 + ci, gk1 = gk0 + 1;
            bool ok0 = Ms[bi][ci] != 0, ok1 = Ms[bi][ci + 1] != 0;
            S[f][0] = (ok0 && gk0 <= q_a) ? S[f][0] : -INFINITY;
            S[f][1] = (ok1 && gk1 <= q_a) ? S[f][1] : -INFINITY;
            S[f][2] = (ok0 && gk0 <= q_b) ? S[f][2] : -INFINITY;
            S[f][3] = (ok1 && gk1 <= q_b) ? S[f][3] : -INFINITY;
            mt_a = fmaxf(mt_a, fmaxf(S[f][0], S[f][1]));
            mt_b = fmaxf(mt_b, fmaxf(S[f][2], S[f][3]));
        }
        mt_a = fmaxf(mt_a, __shfl_xor_sync(0xffffffffu, mt_a, 1));
        mt_a = fmaxf(mt_a, __shfl_xor_sync(0xffffffffu, mt_a, 2));
        mt_b = fmaxf(mt_b, __shfl_xor_sync(0xffffffffu, mt_b, 1));
        mt_b = fmaxf(mt_b, __shfl_xor_sync(0xffffffffu, mt_b, 2));
        float mn_a = fmaxf(m_a, mt_a), mn_b = fmaxf(m_b, mt_b);
        float al_a, al_b, ps_a = 0.f, ps_b = 0.f;
        if (mn_a == -INFINITY) {
            al_a = 1.f;
            #pragma unroll
            for (int f = 0; f < 4; f++) { S[f][0] = 0.f; S[f][1] = 0.f; }
        } else {
            al_a = expf(m_a - mn_a);
            #pragma unroll
            for (int f = 0; f < 4; f++) {
                S[f][0] = expf(S[f][0] - mn_a);
                S[f][1] = expf(S[f][1] - mn_a);
                ps_a += S[f][0] + S[f][1];
            }
        }
        if (mn_b == -INFINITY) {
            al_b = 1.f;
            #pragma unroll
            for (int f = 0; f < 4; f++) { S[f][2] = 0.f; S[f][3] = 0.f; }
        } else {
            al_b = expf(m_b - mn_b);
            #pragma unroll
            for (int f = 0; f < 4; f++) {
                S[f][2] = expf(S[f][2] - mn_b);
                S[f][3] = expf(S[f][3] - mn_b);
                ps_b += S[f][2] + S[f][3];
            }
        }
        ps_a += __shfl_xor_sync(0xffffffffu, ps_a, 1);
        ps_a += __shfl_xor_sync(0xffffffffu, ps_a, 2);
        ps_b += __shfl_xor_sync(0xffffffffu, ps_b, 1);
        ps_b += __shfl_xor_sync(0xffffffffu, ps_b, 2);
        l_a = l_a * al_a + ps_a;
        l_b = l_b * al_b + ps_b;
        m_a = mn_a; m_b = mn_b;
        #pragma unroll
        for (int nf = 0; nf < 8; nf++) {
            O[nf][0] *= al_a; O[nf][1] *= al_a;
            O[nf][2] *= al_b; O[nf][3] *= al_b;
        }

        // ---- O += P V ----
        #pragma unroll
        for (int kc = 0; kc < 2; kc++) {
            int f0 = 2 * kc, f1 = 2 * kc + 1;
            uint32_t pa[4];
            pa[0] = pack_h2(__float2half_rn(S[f0][0]), __float2half_rn(S[f0][1]));
            pa[1] = pack_h2(__float2half_rn(S[f0][2]), __float2half_rn(S[f0][3]));
            pa[2] = pack_h2(__float2half_rn(S[f1][0]), __float2half_rn(S[f1][1]));
            pa[3] = pack_h2(__float2half_rn(S[f1][2]), __float2half_rn(S[f1][3]));
            uint32_t vf[16];
            #pragma unroll
            for (int p4 = 0; p4 < 4; p4++)
                ldsm4(&vf[4 * p4], vAddr + p4 * 16 * (VSTR * 2) + kc * 32);
            #pragma unroll
            for (int nf = 0; nf < 8; nf++)
                mma16816(O[nf], pa, &vf[2 * nf]);
        }
    }

    float rl_a = (l_a > 0.f) ? (1.f / l_a) : 0.f;
    float rl_b = (l_b > 0.f) ? (1.f / l_b) : 0.f;
    size_t rowA = (size_t)(b * T_) + qt * 64 + wid * 16 + grp;
    size_t rowB = rowA + 8;
    #pragma unroll
    for (int nf = 0; nf < 8; nf++) {
        int col = h * DH_ + nf * 8 + qd * 2;
        *(__half2*)(outh + rowA * D_ + col) = __halves2half2(
            __float2half_rn(O[nf][0] * rl_a), __float2half_rn(O[nf][1] * rl_a));
        *(__half2*)(outh + rowB * D_ + col) = __halves2half2(
            __float2half_rn(O[nf][2] * rl_b), __float2half_rn(O[nf][3] * rl_b));
    }
}

// ---------------- head ----------------
__global__ void head_kernel(const float* __restrict__ xn, const int* __restrict__ lastidx,
                            const float* __restrict__ hw, const float* __restrict__ hb,
                            float* __restrict__ out) {
    int b = blockIdx.x;
    int w = threadIdx.x >> 5;
    int lane = threadIdx.x & 31;
    const float* h = xn + ((size_t)(b * T_ + lastidx[b])) * D_;
    float s = 0.f;
    for (int d = lane; d < D_; d += 32) s += h[d] * hw[d * 9 + w];
    #pragma unroll
    for (int o = 16; o; o >>= 1) s += __shfl_down_sync(0xffffffffu, s, o);
    if (lane == 0) out[b * 9 + w] = s + hb[w];
}

// ---------------- orchestration ----------------
extern "C" void kernel_launch(void* const* d_in, const int* in_sizes, int n_in,
                              void* d_out, int out_size) {
    const int*   cards   = (const int*)  d_in[0];
    const int*   players = (const int*)  d_in[1];
    const int*   deck    = (const int*)  d_in[2];
    const int*   opp     = (const int*)  d_in[3];
    const float* tok     = (const float*)d_in[4];
    const float* pemb    = (const float*)d_in[5];
    const float* pos     = (const float*)d_in[6];
    const float* ln1s = (const float*)d_in[9];
    const float* ln1b = (const float*)d_in[10];
    const float* qkvw = (const float*)d_in[11];
    const float* qkvb = (const float*)d_in[12];
    const float* projw = (const float*)d_in[13];
    const float* projb = (const float*)d_in[14];
    const float* ln2s = (const float*)d_in[15];
    const float* ln2b = (const float*)d_in[16];
    const float* fc1w = (const float*)d_in[17];
    const float* fc1b = (const float*)d_in[18];
    const float* fc2w = (const float*)d_in[19];
    const float* fc2b = (const float*)d_in[20];
    const float* lnfs = (const float*)d_in[21];
    const float* lnfb = (const float*)d_in[22];
    const float* headw = (const float*)d_in[23];
    const float* headb = (const float*)d_in[24];

    float *x, *xn, *dm;
    f16 *qkv, *xh, *yh, *hh;
    f16 *qT, *pT, *f1T, *f2T;
    char* mask; int* lastidx;
    cudaGetSymbolAddress((void**)&x,    g_x);
    cudaGetSymbolAddress((void**)&xn,   g_xn);
    cudaGetSymbolAddress((void**)&qkv,  g_qkv);
    cudaGetSymbolAddress((void**)&dm,   g_dm);
    cudaGetSymbolAddress((void**)&xh,   g_xh);
    cudaGetSymbolAddress((void**)&yh,   g_yh);
    cudaGetSymbolAddress((void**)&hh,   g_hh);
    cudaGetSymbolAddress((void**)&qT,   g_qkvT);
    cudaGetSymbolAddress((void**)&pT,   g_projT);
    cudaGetSymbolAddress((void**)&f1T,  g_fc1T);
    cudaGetSymbolAddress((void**)&f2T,  g_fc2T);
    cudaGetSymbolAddress((void**)&mask, g_mask);
    cudaGetSymbolAddress((void**)&lastidx, g_lastidx);

    cudaFuncSetAttribute((const void*)gemm_mma<0, 256>,
                         cudaFuncAttributeMaxDynamicSharedMemorySize, GCfg<256>::SMEM);
    cudaFuncSetAttribute((const void*)gemm_mma<1, 128>,
                         cudaFuncAttributeMaxDynamicSharedMemorySize, GCfg<128>::SMEM);
    cudaFuncSetAttribute((const void*)gemm_mma<2, 128>,
                         cudaFuncAttributeMaxDynamicSharedMemorySize, GCfg<128>::SMEM);

    dim3 tb(32, 8);
    transpose_all<<<TFC2, tb>>>(qkvw, projw, fc1w, fc2w, qT, pT, f1T, f2T);
    mask_kernel<<<B_, T_>>>(cards, mask, lastidx);
    deckmean_kernel<<<B_, D_>>>(deck, opp, tok, dm);
    embed_kernel<<<BT_, 256>>>(cards, players, tok, pemb, pos, dm, x);

    for (int i = 0; i < L_; i++) {
        ln_kernel<true><<<BT_, 256>>>(x, ln1s + i * D_, ln1b + i * D_, nullptr, xh);
        gemm_mma<0, 256><<<dim3(D3_ / 256, BT_ / 128), 256, GCfg<256>::SMEM>>>(
            xh, qT + (size_t)i * D3_ * D_,
            qkvb + i * D3_, nullptr, nullptr, qkv, D_, D3_);
        attn_kernel<<<dim3(T_ / 64, NH_, B_), 128>>>(qkv, mask, yh);
        gemm_mma<2, 128><<<dim3(D_ / 128, BT_ / 128), 256, GCfg<128>::SMEM>>>(
            yh, pT + (size_t)i * D_ * D_,
            projb + i * D_, x, x, nullptr, D_, D_);
        ln_kernel<true><<<BT_, 256>>>(x, ln2s + i * D_, ln2b + i * D_, nullptr, xh);
        gemm_mma<1, 128><<<dim3(D4_ / 128, BT_ / 128), 256, GCfg<128>::SMEM>>>(
            xh, f1T + (size_t)i * D4_ * D_,
            fc1b + i * D4_, nullptr, nullptr, hh, D_, D4_);
        gemm_mma<2, 128><<<dim3(D_ / 128, BT_ / 128), 256, GCfg<128>::SMEM>>>(
            hh, f2T + (size_t)i * D_ * D4_,
            fc2b + i * D_, x, x, nullptr, D4_, D_);
    }

    ln_kernel<false><<<BT_, 256>>>(x, lnfs, lnfb, xn, nullptr);
    head_kernel<<<B_, 288>>>(xn, lastidx, headw, headb, (float*)d_out);
}

// round 16
// speedup vs baseline: 1.3103x; 1.1060x over previous
#include <cuda_runtime.h>
#include <cuda_fp16.h>
#include <math.h>
#include <stdint.h>

typedef __half f16;

// ---------------- problem constants ----------------
#define L_   6
#define D_   768
#define NH_  12
#define DH_  64
#define T_   512
#define B_   16
#define BT_  (B_ * T_)       // 8192
#define D3_  (3 * D_)        // 2304
#define D4_  (4 * D_)        // 3072

// ---------------- scratch ----------------
__device__ __align__(128) float g_x  [BT_ * D_];
__device__ __align__(128) float g_xn [BT_ * D_];
__device__ __align__(128) f16   g_qkv[BT_ * D3_];
__device__ __align__(128) f16   g_xh [BT_ * D_];
__device__ __align__(128) f16   g_yh [BT_ * D_];
__device__ __align__(128) f16   g_hh [BT_ * D4_];
__device__ __align__(128) float g_dm [B_ * D_];
__device__ char  g_mask[B_ * T_];
__device__ int   g_lastidx[B_];

__device__ __align__(128) f16 g_qkvT [L_ * D3_ * D_];
__device__ __align__(128) f16 g_projT[L_ * D_ * D_];
__device__ __align__(128) f16 g_fc1T [L_ * D4_ * D_];
__device__ __align__(128) f16 g_fc2T [L_ * D_ * D4_];

// ---------------- PTX helpers ----------------
__device__ __forceinline__ uint32_t smem_u32(const void* p) {
    uint32_t a;
    asm("{ .reg .u64 t; cvta.to.shared.u64 t, %1; cvt.u32.u64 %0, t; }" : "=r"(a) : "l"(p));
    return a;
}
__device__ __forceinline__ void cp16(uint32_t s, const void* g) {
    asm volatile("cp.async.cg.shared.global [%0], [%1], 16;" :: "r"(s), "l"(g) : "memory");
}
__device__ __forceinline__ void ldsm4(uint32_t* r, uint32_t addr) {
    asm volatile("ldmatrix.sync.aligned.m8n8.x4.shared.b16 {%0,%1,%2,%3}, [%4];"
                 : "=r"(r[0]), "=r"(r[1]), "=r"(r[2]), "=r"(r[3]) : "r"(addr));
}
__device__ __forceinline__ void mma16816(float* c, const uint32_t* a, const uint32_t* b) {
    asm volatile(
        "mma.sync.aligned.m16n8k16.row.col.f32.f16.f16.f32 "
        "{%0,%1,%2,%3}, {%4,%5,%6,%7}, {%8,%9}, {%0,%1,%2,%3};"
        : "+f"(c[0]), "+f"(c[1]), "+f"(c[2]), "+f"(c[3])
        : "r"(a[0]), "r"(a[1]), "r"(a[2]), "r"(a[3]), "r"(b[0]), "r"(b[1]));
}
__device__ __forceinline__ float gelu_exact(float v) {
    return 0.5f * v * (1.0f + erff(v * 0.70710678118654752440f));
}
__device__ __forceinline__ uint32_t pack_h2(f16 a, f16 b) {
    __half2 t = __halves2half2(a, b);
    return *(uint32_t*)&t;
}

// ---------------- fused weight transpose + fp16 round ----------------
#define TQKV (L_ * 1728)
#define TPROJ (TQKV + L_ * 576)
#define TFC1 (TPROJ + L_ * 2304)
#define TFC2 (TFC1 + L_ * 2304)

__global__ void transpose_all(const float* __restrict__ qkvw, const float* __restrict__ projw,
                              const float* __restrict__ fc1w, const float* __restrict__ fc2w,
                              f16* __restrict__ qT, f16* __restrict__ pT,
                              f16* __restrict__ f1T, f16* __restrict__ f2T) {
    __shared__ float tile[32][33];
    int idx = blockIdx.x;
    const float* W; f16* Th; int K, N, rem;
    if (idx < TQKV) {
        int layer = idx / 1728; rem = idx % 1728;
        K = D_; N = D3_;
        W = qkvw + (size_t)layer * D_ * D3_;
        Th = qT + (size_t)layer * D3_ * D_;
    } else if (idx < TPROJ) {
        idx -= TQKV;
        int layer = idx / 576; rem = idx % 576;
        K = D_; N = D_;
        W = projw + (size_t)layer * D_ * D_;
        Th = pT + (size_t)layer * D_ * D_;
    } else if (idx < TFC1) {
        idx -= TPROJ;
        int layer = idx / 2304; rem = idx % 2304;
        K = D_; N = D4_;
        W = fc1w + (size_t)layer * D_ * D4_;
        Th = f1T + (size_t)layer * D4_ * D_;
    } else {
        idx -= TFC1;
        int layer = idx / 2304; rem = idx % 2304;
        K = D4_; N = D_;
        W = fc2w + (size_t)layer * D4_ * D_;
        Th = f2T + (size_t)layer * D_ * D4_;
    }
    int tilesN = N >> 5;
    int n0 = (rem % tilesN) << 5;
    int k0 = (rem / tilesN) << 5;
    int tx = threadIdx.x, ty = threadIdx.y;
    #pragma unroll
    for (int i = 0; i < 32; i += 8)
        tile[ty + i][tx] = W[(size_t)(k0 + ty + i) * N + n0 + tx];
    __syncthreads();
    #pragma unroll
    for (int i = 0; i < 32; i += 8) {
        float v = tile[tx][ty + i];
        Th[(size_t)(n0 + ty + i) * K + k0 + tx] = __float2half_rn(v);
    }
}

// ---------------- mask + last_idx ----------------
__global__ void mask_kernel(const int* __restrict__ cards,
                            char* __restrict__ mask, int* __restrict__ lastidx) {
    int b = blockIdx.x;
    int t = threadIdx.x;
    bool valid = cards[b * T_ + t] != 0;
    bool any = __syncthreads_or(valid);
    bool m = valid || (t == 0 && !any);
    mask[b * T_ + t] = m ? 1 : 0;
    int cnt = __syncthreads_count(m);
    if (t == 0) lastidx[b] = (cnt - 1) > 0 ? (cnt - 1) : 0;
}

// ---------------- deck means ----------------
__global__ void deckmean_kernel(const int* __restrict__ deck, const int* __restrict__ opp,
                                const float* __restrict__ tok, float* __restrict__ dm) {
    int b = blockIdx.x;
    int d = threadIdx.x;
    float s = 0.f;
    #pragma unroll
    for (int i = 0; i < 8; i++) {
        s += tok[(size_t)deck[b * 8 + i] * D_ + d];
        s += tok[(size_t)opp [b * 8 + i] * D_ + d];
    }
    dm[b * D_ + d] = s * 0.125f;
}

// ---------------- embedding sum ----------------
__global__ void embed_kernel(const int* __restrict__ cards, const int* __restrict__ players,
                             const float* __restrict__ tok, const float* __restrict__ pemb,
                             const float* __restrict__ pos, const float* __restrict__ dm,
                             float* __restrict__ x) {
    int bt = blockIdx.x;
    int b = bt >> 9;
    int t = bt & 511;
    int card = cards[bt];
    int pl = players[bt]; pl = pl < 0 ? 0 : (pl > 1 ? 1 : pl);
    const float* tr = tok  + (size_t)card * D_;
    const float* pr = pemb + (size_t)pl * D_;
    const float* qr = pos  + (size_t)t * D_;
    const float* mr = dm   + (size_t)b * D_;
    float* xr = x + (size_t)bt * D_;
    for (int d = threadIdx.x; d < D_; d += 256)
        xr[d] = tr[d] + pr[d] + mr[d] + qr[d];
}

// ---------------- layernorm (float4), 256 thr / row, 192 active loaders ------------
template<bool TOH>
__global__ void ln_kernel(const float* __restrict__ x, const float* __restrict__ g,
                          const float* __restrict__ be, float* __restrict__ of,
                          f16* __restrict__ oh) {
    __shared__ float sh1[8], sh2[8];
    int r = blockIdx.x;
    size_t base = (size_t)r * D_;
    int t = threadIdx.x;
    float4 v = make_float4(0.f, 0.f, 0.f, 0.f);
    if (t < 192) v = *(const float4*)(x + base + 4 * t);
    float s = v.x + v.y + v.z + v.w;
    float q = v.x * v.x + v.y * v.y + v.z * v.z + v.w * v.w;
    #pragma unroll
    for (int o2 = 16; o2; o2 >>= 1) {
        s += __shfl_xor_sync(0xffffffffu, s, o2);
        q += __shfl_xor_sync(0xffffffffu, q, o2);
    }
    if ((t & 31) == 0) { sh1[t >> 5] = s; sh2[t >> 5] = q; }
    __syncthreads();
    s = sh1[t & 7]; q = sh2[t & 7];
    #pragma unroll
    for (int o2 = 4; o2; o2 >>= 1) {
        s += __shfl_xor_sync(0xffffffffu, s, o2);
        q += __shfl_xor_sync(0xffffffffu, q, o2);
    }
    float mean = s * (1.0f / D_);
    float var  = q * (1.0f / D_) - mean * mean;
    float rstd = rsqrtf(var + 1e-5f);
    if (t < 192) {
        int d = 4 * t;
        float4 gv = *(const float4*)(g + d);
        float4 bv = *(const float4*)(be + d);
        float o0 = (v.x - mean) * rstd * gv.x + bv.x;
        float o1 = (v.y - mean) * rstd * gv.y + bv.y;
        float o2_ = (v.z - mean) * rstd * gv.z + bv.z;
        float o3 = (v.w - mean) * rstd * gv.w + bv.w;
        if (TOH) {
            __half2 h0 = __halves2half2(__float2half_rn(o0), __float2half_rn(o1));
            __half2 h1 = __halves2half2(__float2half_rn(o2_), __float2half_rn(o3));
            uint2 pk; pk.x = *(uint32_t*)&h0; pk.y = *(uint32_t*)&h1;
            *(uint2*)(oh + base + d) = pk;
        } else {
            *(float4*)(of + base + d) = make_float4(o0, o1, o2_, o3);
        }
    }
}

// ---------------- mma.sync fp16 GEMM (BK=32, 4-stage ring, 1 sync/kt) --------------
// BN=128 kernels: 2 CTAs/SM (163 KB smem total) for cross-CTA latency hiding.
// EPI: 0 = bias -> f16; 1 = bias+gelu -> f16; 2 = bias+residual -> fp32
#define ROWB 80
template<int BN> struct GCfg {
    static constexpr int A_OFF = 0;
    static constexpr int B_OFF = 128 * ROWB;
    static constexpr int STAGE = (128 + BN) * ROWB;
    static constexpr int SMEM  = 4 * STAGE;          // BN=256: 122880; BN=128: 81920
    static constexpr int NF    = BN / 32;
    static constexpr int NPW   = BN / 4;
    static constexpr int OCC   = (BN == 128) ? 2 : 1;
};

template<int EPI, int BN>
__global__ __launch_bounds__(256, GCfg<BN>::OCC)
void gemm_mma(const f16* __restrict__ Ah, const f16* __restrict__ Bh,
              const float* __restrict__ bias, const float* __restrict__ res,
              float* __restrict__ outf, f16* __restrict__ outh,
              int K, int Nfull) {
    using C = GCfg<BN>;
    extern __shared__ char dsm[];
    uint32_t tiles = smem_u32(dsm);

    int tid = threadIdx.x;
    int wid = tid >> 5;
    int lane = tid & 31;
    int warp_m = wid & 1;
    int warp_n = wid >> 1;
    int m0 = blockIdx.y * 128;
    int n0 = blockIdx.x * BN;
    int nt = K >> 5;

    int aRow  = lane & 15;
    int aColB = (lane >> 4) << 4;
    int bRow  = (lane & 7) + ((lane & 16) >> 1);
    int bColB = (lane & 8) << 1;

    float acc[4][C::NF][4];
    #pragma unroll
    for (int mt = 0; mt < 4; mt++)
        #pragma unroll
        for (int ntl = 0; ntl < C::NF; ntl++)
            #pragma unroll
            for (int r = 0; r < 4; r++) acc[mt][ntl][r] = 0.f;

    auto load_stage = [&](int kt, int st) {
        uint32_t sb = tiles + st * C::STAGE;
        int k0 = kt << 5;
        #pragma unroll
        for (int i = 0; i < 2; i++) {
            int id = tid + (i << 8);
            int r = id >> 2, c = id & 3;
            size_t go = (size_t)(m0 + r) * K + k0 + (c << 3);
            cp16(sb + C::A_OFF + r * ROWB + (c << 4), Ah + go);
        }
        #pragma unroll
        for (int i = 0; i < BN / 64; i++) {
            int id = tid + (i << 8);
            int r = id >> 2, c = id & 3;
            size_t go = (size_t)(n0 + r) * K + k0 + (c << 3);
            cp16(sb + C::B_OFF + r * ROWB + (c << 4), Bh + go);
        }
        asm volatile("cp.async.commit_group;" ::: "memory");
    };

    load_stage(0, 0);
    load_stage(1, 1);

    uint32_t aH[16], bH[2 * C::NF];

    for (int kt = 0; kt < nt; kt++) {
        int cur = kt & 3;
        if (kt + 2 < nt) {
            load_stage(kt + 2, (kt + 2) & 3);
            asm volatile("cp.async.wait_group 2;" ::: "memory");
        } else if (kt + 1 < nt) {
            asm volatile("cp.async.wait_group 1;" ::: "memory");
        } else {
            asm volatile("cp.async.wait_group 0;" ::: "memory");
        }
        __syncthreads();

        uint32_t sb = tiles + cur * C::STAGE;
        uint32_t aBase = sb + (warp_m * 64 + aRow) * ROWB + aColB;
        uint32_t bBase = sb + C::B_OFF + (warp_n * C::NPW + bRow) * ROWB + bColB;

        #pragma unroll
        for (int ks = 0; ks < 2; ks++) {
            uint32_t kb = ks << 5;
            #pragma unroll
            for (int mt = 0; mt < 4; mt++)
                ldsm4(&aH[4 * mt], aBase + mt * (16 * ROWB) + kb);
            #pragma unroll
            for (int p = 0; p < BN / 64; p++)
                ldsm4(&bH[4 * p], bBase + p * (16 * ROWB) + kb);
            #pragma unroll
            for (int mt = 0; mt < 4; mt++)
                #pragma unroll
                for (int ntl = 0; ntl < C::NF; ntl++)
                    mma16816(acc[mt][ntl], &aH[4 * mt], &bH[2 * ntl]);
        }
    }

    int m_base = m0 + warp_m * 64 + (lane >> 2);
    int n_base = n0 + warp_n * C::NPW + ((lane & 3) << 1);
    #pragma unroll
    for (int mt = 0; mt < 4; mt++) {
        #pragma unroll
        for (int ntl = 0; ntl < C::NF; ntl++) {
            int n = n_base + ntl * 8;
            float b0 = bias[n], b1 = bias[n + 1];
            #pragma unroll
            for (int rr = 0; rr < 2; rr++) {
                int m = m_base + mt * 16 + rr * 8;
                size_t ob = (size_t)m * Nfull + n;
                float v0 = acc[mt][ntl][2 * rr]     + b0;
                float v1 = acc[mt][ntl][2 * rr + 1] + b1;
                if (EPI == 0) {
                    *(__half2*)(outh + ob) =
                        __halves2half2(__float2half_rn(v0), __float2half_rn(v1));
                } else if (EPI == 2) {
                    float2 rv = *(const float2*)(res + ob);
                    *(float2*)(outf + ob) = make_float2(v0 + rv.x, v1 + rv.y);
                } else {
                    float g0 = gelu_exact(v0), g1 = gelu_exact(v1);
                    *(__half2*)(outh + ob) =
                        __halves2half2(__float2half_rn(g0), __float2half_rn(g1));
                }
            }
        }
    }
}

// ---------------- tensor-core flash attention (R13 config: single buffer) ----------
#define QSTR 72
#define VSTR 40

__global__ __launch_bounds__(128)
void attn_kernel(const f16* __restrict__ qkv, const char* __restrict__ mask,
                 f16* __restrict__ outh) {
    __shared__ f16 sQ[64 * QSTR];
    __shared__ f16 sK[32 * QSTR];
    __shared__ f16 sV[64 * VSTR];    // V^T: [dim][key]
    __shared__ char Ms[32];

    int qt = blockIdx.x, h = blockIdx.y, b = blockIdx.z;
    int tid = threadIdx.x;
    int wid = tid >> 5, lane = tid & 31;
    int grp = lane >> 2, qd = lane & 3;

    {
        int row = tid >> 1;
        int c0 = (tid & 1) * 32;
        const f16* g = qkv + ((size_t)(b * T_ + qt * 64 + row)) * D3_ + h * DH_ + c0;
        __half2 sc = __half2half2(__float2half(0.125f));
        #pragma unroll
        for (int u = 0; u < 16; u++) {
            __half2 v = *(const __half2*)(g + 2 * u);
            *(__half2*)&sQ[row * QSTR + c0 + 2 * u] = __hmul2(v, sc);
        }
    }

    float O[8][4];
    #pragma unroll
    for (int nf = 0; nf < 8; nf++)
        #pragma unroll
        for (int r = 0; r < 4; r++) O[nf][r] = 0.f;
    float m_a = -INFINITY, m_b = -INFINITY, l_a = 0.f, l_b = 0.f;

    uint32_t aAddr = smem_u32(sQ) + (wid * 16 + (lane & 15)) * (QSTR * 2) + ((lane >> 4) << 4);
    int bRow  = (lane & 7) + ((lane & 16) >> 1);
    int bColB = (lane & 8) << 1;
    uint32_t kAddr = smem_u32(sK) + bRow * (QSTR * 2) + bColB;
    uint32_t vAddr = smem_u32(sV) + bRow * (VSTR * 2) + bColB;

    int q_a = qt * 64 + wid * 16 + grp;
    int q_b = q_a + 8;

    int ktmax = (qt + 1) * 2;
    for (int kt = 0; kt < ktmax; kt++) {
        __syncthreads();
        {
            int j  = tid >> 2;
            int d0 = (tid & 3) * 16;
            const f16* gk = qkv + ((size_t)(b * T_ + kt * 32 + j)) * D3_ + D_ + h * DH_ + d0;
            const f16* gv = gk + D_;
            #pragma unroll
            for (int u = 0; u < 2; u++)
                *(uint4*)&sK[j * QSTR + d0 + u * 8] = *(const uint4*)(gk + u * 8);
            #pragma unroll
            for (int u = 0; u < 8; u++) {
                __half2 v = *(const __half2*)(gv + 2 * u);
                int d = d0 + 2 * u;
                sV[(d + 0) * VSTR + j] = __low2half(v);
                sV[(d + 1) * VSTR + j] = __high2half(v);
            }
            if (tid < 32) Ms[tid] = mask[b * T_ + kt * 32 + tid];
        }
        __syncthreads();

        float S[4][4];
        #pragma unroll
        for (int f = 0; f < 4; f++)
            #pragma unroll
            for (int r = 0; r < 4; r++) S[f][r] = 0.f;
        #pragma unroll
        for (int kc = 0; kc < 4; kc++) {
            uint32_t q[4], kf[8];
            ldsm4(q, aAddr + kc * 32);
            ldsm4(&kf[0], kAddr + kc * 32);
            ldsm4(&kf[4], kAddr + 16 * (QSTR * 2) + kc * 32);
            #pragma unroll
            for (int f = 0; f < 4; f++)
                mma16816(S[f], q, &kf[2 * f]);
        }

        float mt_a = -INFINITY, mt_b = -INFINITY;
        #pragma unroll
        for (int f = 0; f < 4; f++) {
            int ci = f * 8 + qd * 2;
            int gk0 = kt * 32 + ci, gk1 = gk0 + 1;
            bool ok0 = Ms[ci] != 0, ok1 = Ms[ci + 1] != 0;
            S[f][0] = (ok0 && gk0 <= q_a) ? S[f][0] : -INFINITY;
            S[f][1] = (ok1 && gk1 <= q_a) ? S[f][1] : -INFINITY;
            S[f][2] = (ok0 && gk0 <= q_b) ? S[f][2] : -INFINITY;
            S[f][3] = (ok1 && gk1 <= q_b) ? S[f][3] : -INFINITY;
            mt_a = fmaxf(mt_a, fmaxf(S[f][0], S[f][1]));
            mt_b = fmaxf(mt_b, fmaxf(S[f][2], S[f][3]));
        }
        mt_a = fmaxf(mt_a, __shfl_xor_sync(0xffffffffu, mt_a, 1));
        mt_a = fmaxf(mt_a, __shfl_xor_sync(0xffffffffu, mt_a, 2));
        mt_b = fmaxf(mt_b, __shfl_xor_sync(0xffffffffu, mt_b, 1));
        mt_b = fmaxf(mt_b, __shfl_xor_sync(0xffffffffu, mt_b, 2));
        float mn_a = fmaxf(m_a, mt_a), mn_b = fmaxf(m_b, mt_b);
        float al_a, al_b, ps_a = 0.f, ps_b = 0.f;
        if (mn_a == -INFINITY) {
            al_a = 1.f;
            #pragma unroll
            for (int f = 0; f < 4; f++) { S[f][0] = 0.f; S[f][1] = 0.f; }
        } else {
            al_a = expf(m_a - mn_a);
            #pragma unroll
            for (int f = 0; f < 4; f++) {
                S[f][0] = expf(S[f][0] - mn_a);
                S[f][1] = expf(S[f][1] - mn_a);
                ps_a += S[f][0] + S[f][1];
            }
        }
        if (mn_b == -INFINITY) {
            al_b = 1.f;
            #pragma unroll
            for (int f = 0; f < 4; f++) { S[f][2] = 0.f; S[f][3] = 0.f; }
        } else {
            al_b = expf(m_b - mn_b);
            #pragma unroll
            for (int f = 0; f < 4; f++) {
                S[f][2] = expf(S[f][2] - mn_b);
                S[f][3] = expf(S[f][3] - mn_b);
                ps_b += S[f][2] + S[f][3];
            }
        }
        ps_a += __shfl_xor_sync(0xffffffffu, ps_a, 1);
        ps_a += __shfl_xor_sync(0xffffffffu, ps_a, 2);
        ps_b += __shfl_xor_sync(0xffffffffu, ps_b, 1);
        ps_b += __shfl_xor_sync(0xffffffffu, ps_b, 2);
        l_a = l_a * al_a + ps_a;
        l_b = l_b * al_b + ps_b;
        m_a = mn_a; m_b = mn_b;
        #pragma unroll
        for (int nf = 0; nf < 8; nf++) {
            O[nf][0] *= al_a; O[nf][1] *= al_a;
            O[nf][2] *= al_b; O[nf][3] *= al_b;
        }

        #pragma unroll
        for (int kc = 0; kc < 2; kc++) {
            int f0 = 2 * kc, f1 = 2 * kc + 1;
            uint32_t pa[4];
            pa[0] = pack_h2(__float2half_rn(S[f0][0]), __float2half_rn(S[f0][1]));
            pa[1] = pack_h2(__float2half_rn(S[f0][2]), __float2half_rn(S[f0][3]));
            pa[2] = pack_h2(__float2half_rn(S[f1][0]), __float2half_rn(S[f1][1]));
            pa[3] = pack_h2(__float2half_rn(S[f1][2]), __float2half_rn(S[f1][3]));
            uint32_t vf[16];
            #pragma unroll
            for (int p4 = 0; p4 < 4; p4++)
                ldsm4(&vf[4 * p4], vAddr + p4 * 16 * (VSTR * 2) + kc * 32);
            #pragma unroll
            for (int nf = 0; nf < 8; nf++)
                mma16816(O[nf], pa, &vf[2 * nf]);
        }
    }

    float rl_a = (l_a > 0.f) ? (1.f / l_a) : 0.f;
    float rl_b = (l_b > 0.f) ? (1.f / l_b) : 0.f;
    size_t rowA = (size_t)(b * T_) + qt * 64 + wid * 16 + grp;
    size_t rowB = rowA + 8;
    #pragma unroll
    for (int nf = 0; nf < 8; nf++) {
        int col = h * DH_ + nf * 8 + qd * 2;
        *(__half2*)(outh + rowA * D_ + col) = __halves2half2(
            __float2half_rn(O[nf][0] * rl_a), __float2half_rn(O[nf][1] * rl_a));
        *(__half2*)(outh + rowB * D_ + col) = __halves2half2(
            __float2half_rn(O[nf][2] * rl_b), __float2half_rn(O[nf][3] * rl_b));
    }
}

// ---------------- head ----------------
__global__ void head_kernel(const float* __restrict__ xn, const int* __restrict__ lastidx,
                            const float* __restrict__ hw, const float* __restrict__ hb,
                            float* __restrict__ out) {
    int b = blockIdx.x;
    int w = threadIdx.x >> 5;
    int lane = threadIdx.x & 31;
    const float* h = xn + ((size_t)(b * T_ + lastidx[b])) * D_;
    float s = 0.f;
    for (int d = lane; d < D_; d += 32) s += h[d] * hw[d * 9 + w];
    #pragma unroll
    for (int o = 16; o; o >>= 1) s += __shfl_down_sync(0xffffffffu, s, o);
    if (lane == 0) out[b * 9 + w] = s + hb[w];
}

// ---------------- orchestration ----------------
extern "C" void kernel_launch(void* const* d_in, const int* in_sizes, int n_in,
                              void* d_out, int out_size) {
    const int*   cards   = (const int*)  d_in[0];
    const int*   players = (const int*)  d_in[1];
    const int*   deck    = (const int*)  d_in[2];
    const int*   opp     = (const int*)  d_in[3];
    const float* tok     = (const float*)d_in[4];
    const float* pemb    = (const float*)d_in[5];
    const float* pos     = (const float*)d_in[6];
    const float* ln1s = (const float*)d_in[9];
    const float* ln1b = (const float*)d_in[10];
    const float* qkvw = (const float*)d_in[11];
    const float* qkvb = (const float*)d_in[12];
    const float* projw = (const float*)d_in[13];
    const float* projb = (const float*)d_in[14];
    const float* ln2s = (const float*)d_in[15];
    const float* ln2b = (const float*)d_in[16];
    const float* fc1w = (const float*)d_in[17];
    const float* fc1b = (const float*)d_in[18];
    const float* fc2w = (const float*)d_in[19];
    const float* fc2b = (const float*)d_in[20];
    const float* lnfs = (const float*)d_in[21];
    const float* lnfb = (const float*)d_in[22];
    const float* headw = (const float*)d_in[23];
    const float* headb = (const float*)d_in[24];

    float *x, *xn, *dm;
    f16 *qkv, *xh, *yh, *hh;
    f16 *qT, *pT, *f1T, *f2T;
    char* mask; int* lastidx;
    cudaGetSymbolAddress((void**)&x,    g_x);
    cudaGetSymbolAddress((void**)&xn,   g_xn);
    cudaGetSymbolAddress((void**)&qkv,  g_qkv);
    cudaGetSymbolAddress((void**)&dm,   g_dm);
    cudaGetSymbolAddress((void**)&xh,   g_xh);
    cudaGetSymbolAddress((void**)&yh,   g_yh);
    cudaGetSymbolAddress((void**)&hh,   g_hh);
    cudaGetSymbolAddress((void**)&qT,   g_qkvT);
    cudaGetSymbolAddress((void**)&pT,   g_projT);
    cudaGetSymbolAddress((void**)&f1T,  g_fc1T);
    cudaGetSymbolAddress((void**)&f2T,  g_fc2T);
    cudaGetSymbolAddress((void**)&mask, g_mask);
    cudaGetSymbolAddress((void**)&lastidx, g_lastidx);

    cudaFuncSetAttribute((const void*)gemm_mma<0, 256>,
                         cudaFuncAttributeMaxDynamicSharedMemorySize, GCfg<256>::SMEM);
    cudaFuncSetAttribute((const void*)gemm_mma<1, 128>,
                         cudaFuncAttributeMaxDynamicSharedMemorySize, GCfg<128>::SMEM);
    cudaFuncSetAttribute((const void*)gemm_mma<2, 128>,
                         cudaFuncAttributeMaxDynamicSharedMemorySize, GCfg<128>::SMEM);

    dim3 tb(32, 8);
    transpose_all<<<TFC2, tb>>>(qkvw, projw, fc1w, fc2w, qT, pT, f1T, f2T);
    mask_kernel<<<B_, T_>>>(cards, mask, lastidx);
    deckmean_kernel<<<B_, D_>>>(deck, opp, tok, dm);
    embed_kernel<<<BT_, 256>>>(cards, players, tok, pemb, pos, dm, x);

    for (int i = 0; i < L_; i++) {
        ln_kernel<true><<<BT_, 256>>>(x, ln1s + i * D_, ln1b + i * D_, nullptr, xh);
        gemm_mma<0, 256><<<dim3(D3_ / 256, BT_ / 128), 256, GCfg<256>::SMEM>>>(
            xh, qT + (size_t)i * D3_ * D_,
            qkvb + i * D3_, nullptr, nullptr, qkv, D_, D3_);
        attn_kernel<<<dim3(T_ / 64, NH_, B_), 128>>>(qkv, mask, yh);
        gemm_mma<2, 128><<<dim3(D_ / 128, BT_ / 128), 256, GCfg<128>::SMEM>>>(
            yh, pT + (size_t)i * D_ * D_,
            projb + i * D_, x, x, nullptr, D_, D_);
        ln_kernel<true><<<BT_, 256>>>(x, ln2s + i * D_, ln2b + i * D_, nullptr, xh);
        gemm_mma<1, 128><<<dim3(D4_ / 128, BT_ / 128), 256, GCfg<128>::SMEM>>>(
            xh, f1T + (size_t)i * D4_ * D_,
            fc1b + i * D4_, nullptr, nullptr, hh, D_, D4_);
        gemm_mma<2, 128><<<dim3(D_ / 128, BT_ / 128), 256, GCfg<128>::SMEM>>>(
            hh, f2T + (size_t)i * D_ * D4_,
            fc2b + i * D_, x, x, nullptr, D4_, D_);
    }

    ln_kernel<false><<<BT_, 256>>>(x, lnfs, lnfb, xn, nullptr);
    head_kernel<<<B_, 288>>>(xn, lastidx, headw, headb, (float*)d_out);
}

// round 17
// speedup vs baseline: 1.3110x; 1.0005x over previous
#include <cuda_runtime.h>
#include <cuda_fp16.h>
#include <math.h>
#include <stdint.h>

typedef __half f16;

// ---------------- problem constants ----------------
#define L_   6
#define D_   768
#define NH_  12
#define DH_  64
#define T_   512
#define B_   16
#define BT_  (B_ * T_)       // 8192
#define D3_  (3 * D_)        // 2304
#define D4_  (4 * D_)        // 3072

// ---------------- scratch ----------------
__device__ __align__(128) float g_x  [BT_ * D_];
__device__ __align__(128) float g_xn [BT_ * D_];
__device__ __align__(128) f16   g_qkv[BT_ * D3_];
__device__ __align__(128) f16   g_xh [BT_ * D_];
__device__ __align__(128) f16   g_yh [BT_ * D_];
__device__ __align__(128) f16   g_hh [BT_ * D4_];
__device__ __align__(128) float g_dm [B_ * D_];
__device__ char  g_mask[B_ * T_];
__device__ int   g_lastidx[B_];

__device__ __align__(128) f16 g_qkvT [L_ * D3_ * D_];
__device__ __align__(128) f16 g_projT[L_ * D_ * D_];
__device__ __align__(128) f16 g_fc1T [L_ * D4_ * D_];
__device__ __align__(128) f16 g_fc2T [L_ * D_ * D4_];

// ---------------- PTX helpers ----------------
__device__ __forceinline__ uint32_t smem_u32(const void* p) {
    uint32_t a;
    asm("{ .reg .u64 t; cvta.to.shared.u64 t, %1; cvt.u32.u64 %0, t; }" : "=r"(a) : "l"(p));
    return a;
}
__device__ __forceinline__ void cp16(uint32_t s, const void* g) {
    asm volatile("cp.async.cg.shared.global [%0], [%1], 16;" :: "r"(s), "l"(g) : "memory");
}
__device__ __forceinline__ void ldsm4(uint32_t* r, uint32_t addr) {
    asm volatile("ldmatrix.sync.aligned.m8n8.x4.shared.b16 {%0,%1,%2,%3}, [%4];"
                 : "=r"(r[0]), "=r"(r[1]), "=r"(r[2]), "=r"(r[3]) : "r"(addr));
}
__device__ __forceinline__ void mma16816(float* c, const uint32_t* a, const uint32_t* b) {
    asm volatile(
        "mma.sync.aligned.m16n8k16.row.col.f32.f16.f16.f32 "
        "{%0,%1,%2,%3}, {%4,%5,%6,%7}, {%8,%9}, {%0,%1,%2,%3};"
        : "+f"(c[0]), "+f"(c[1]), "+f"(c[2]), "+f"(c[3])
        : "r"(a[0]), "r"(a[1]), "r"(a[2]), "r"(a[3]), "r"(b[0]), "r"(b[1]));
}
__device__ __forceinline__ float gelu_exact(float v) {
    return 0.5f * v * (1.0f + erff(v * 0.70710678118654752440f));
}
__device__ __forceinline__ uint32_t pack_h2(f16 a, f16 b) {
    __half2 t = __halves2half2(a, b);
    return *(uint32_t*)&t;
}

// ---------------- fused weight transpose + fp16 round ----------------
#define TQKV (L_ * 1728)
#define TPROJ (TQKV + L_ * 576)
#define TFC1 (TPROJ + L_ * 2304)
#define TFC2 (TFC1 + L_ * 2304)

__global__ void transpose_all(const float* __restrict__ qkvw, const float* __restrict__ projw,
                              const float* __restrict__ fc1w, const float* __restrict__ fc2w,
                              f16* __restrict__ qT, f16* __restrict__ pT,
                              f16* __restrict__ f1T, f16* __restrict__ f2T) {
    __shared__ float tile[32][33];
    int idx = blockIdx.x;
    const float* W; f16* Th; int K, N, rem;
    if (idx < TQKV) {
        int layer = idx / 1728; rem = idx % 1728;
        K = D_; N = D3_;
        W = qkvw + (size_t)layer * D_ * D3_;
        Th = qT + (size_t)layer * D3_ * D_;
    } else if (idx < TPROJ) {
        idx -= TQKV;
        int layer = idx / 576; rem = idx % 576;
        K = D_; N = D_;
        W = projw + (size_t)layer * D_ * D_;
        Th = pT + (size_t)layer * D_ * D_;
    } else if (idx < TFC1) {
        idx -= TPROJ;
        int layer = idx / 2304; rem = idx % 2304;
        K = D_; N = D4_;
        W = fc1w + (size_t)layer * D_ * D4_;
        Th = f1T + (size_t)layer * D4_ * D_;
    } else {
        idx -= TFC1;
        int layer = idx / 2304; rem = idx % 2304;
        K = D4_; N = D_;
        W = fc2w + (size_t)layer * D4_ * D_;
        Th = f2T + (size_t)layer * D_ * D4_;
    }
    int tilesN = N >> 5;
    int n0 = (rem % tilesN) << 5;
    int k0 = (rem / tilesN) << 5;
    int tx = threadIdx.x, ty = threadIdx.y;
    #pragma unroll
    for (int i = 0; i < 32; i += 8)
        tile[ty + i][tx] = W[(size_t)(k0 + ty + i) * N + n0 + tx];
    __syncthreads();
    #pragma unroll
    for (int i = 0; i < 32; i += 8) {
        float v = tile[tx][ty + i];
        Th[(size_t)(n0 + ty + i) * K + k0 + tx] = __float2half_rn(v);
    }
}

// ---------------- mask + last_idx ----------------
__global__ void mask_kernel(const int* __restrict__ cards,
                            char* __restrict__ mask, int* __restrict__ lastidx) {
    int b = blockIdx.x;
    int t = threadIdx.x;
    bool valid = cards[b * T_ + t] != 0;
    bool any = __syncthreads_or(valid);
    bool m = valid || (t == 0 && !any);
    mask[b * T_ + t] = m ? 1 : 0;
    int cnt = __syncthreads_count(m);
    if (t == 0) lastidx[b] = (cnt - 1) > 0 ? (cnt - 1) : 0;
}

// ---------------- deck means ----------------
__global__ void deckmean_kernel(const int* __restrict__ deck, const int* __restrict__ opp,
                                const float* __restrict__ tok, float* __restrict__ dm) {
    int b = blockIdx.x;
    int d = threadIdx.x;
    float s = 0.f;
    #pragma unroll
    for (int i = 0; i < 8; i++) {
        s += tok[(size_t)deck[b * 8 + i] * D_ + d];
        s += tok[(size_t)opp [b * 8 + i] * D_ + d];
    }
    dm[b * D_ + d] = s * 0.125f;
}

// ---------------- embedding sum ----------------
__global__ void embed_kernel(const int* __restrict__ cards, const int* __restrict__ players,
                             const float* __restrict__ tok, const float* __restrict__ pemb,
                             const float* __restrict__ pos, const float* __restrict__ dm,
                             float* __restrict__ x) {
    int bt = blockIdx.x;
    int b = bt >> 9;
    int t = bt & 511;
    int card = cards[bt];
    int pl = players[bt]; pl = pl < 0 ? 0 : (pl > 1 ? 1 : pl);
    const float* tr = tok  + (size_t)card * D_;
    const float* pr = pemb + (size_t)pl * D_;
    const float* qr = pos  + (size_t)t * D_;
    const float* mr = dm   + (size_t)b * D_;
    float* xr = x + (size_t)bt * D_;
    for (int d = threadIdx.x; d < D_; d += 256)
        xr[d] = tr[d] + pr[d] + mr[d] + qr[d];
}

// ---------------- layernorm (float4), 256 thr / row, 192 active loaders ------------
template<bool TOH>
__global__ void ln_kernel(const float* __restrict__ x, const float* __restrict__ g,
                          const float* __restrict__ be, float* __restrict__ of,
                          f16* __restrict__ oh) {
    __shared__ float sh1[8], sh2[8];
    int r = blockIdx.x;
    size_t base = (size_t)r * D_;
    int t = threadIdx.x;
    float4 v = make_float4(0.f, 0.f, 0.f, 0.f);
    if (t < 192) v = *(const float4*)(x + base + 4 * t);
    float s = v.x + v.y + v.z + v.w;
    float q = v.x * v.x + v.y * v.y + v.z * v.z + v.w * v.w;
    #pragma unroll
    for (int o2 = 16; o2; o2 >>= 1) {
        s += __shfl_xor_sync(0xffffffffu, s, o2);
        q += __shfl_xor_sync(0xffffffffu, q, o2);
    }
    if ((t & 31) == 0) { sh1[t >> 5] = s; sh2[t >> 5] = q; }
    __syncthreads();
    s = sh1[t & 7]; q = sh2[t & 7];
    #pragma unroll
    for (int o2 = 4; o2; o2 >>= 1) {
        s += __shfl_xor_sync(0xffffffffu, s, o2);
        q += __shfl_xor_sync(0xffffffffu, q, o2);
    }
    float mean = s * (1.0f / D_);
    float var  = q * (1.0f / D_) - mean * mean;
    float rstd = rsqrtf(var + 1e-5f);
    if (t < 192) {
        int d = 4 * t;
        float4 gv = *(const float4*)(g + d);
        float4 bv = *(const float4*)(be + d);
        float o0 = (v.x - mean) * rstd * gv.x + bv.x;
        float o1 = (v.y - mean) * rstd * gv.y + bv.y;
        float o2_ = (v.z - mean) * rstd * gv.z + bv.z;
        float o3 = (v.w - mean) * rstd * gv.w + bv.w;
        if (TOH) {
            __half2 h0 = __halves2half2(__float2half_rn(o0), __float2half_rn(o1));
            __half2 h1 = __halves2half2(__float2half_rn(o2_), __float2half_rn(o3));
            uint2 pk; pk.x = *(uint32_t*)&h0; pk.y = *(uint32_t*)&h1;
            *(uint2*)(oh + base + d) = pk;
        } else {
            *(float4*)(of + base + d) = make_float4(o0, o1, o2_, o3);
        }
    }
}

// ---------------- mma.sync fp16 GEMM (BK=32, 4-stage ring, 1 sync/kt, occ-2) -------
// All GEMMs now BN=128 with 2 CTAs/SM (163 KB smem total) for cross-CTA hiding.
// EPI: 0 = bias -> f16; 1 = bias+gelu -> f16; 2 = bias+residual -> fp32
#define ROWB 80
template<int BN> struct GCfg {
    static constexpr int A_OFF = 0;
    static constexpr int B_OFF = 128 * ROWB;
    static constexpr int STAGE = (128 + BN) * ROWB;
    static constexpr int SMEM  = 4 * STAGE;          // BN=128: 81920
    static constexpr int NF    = BN / 32;
    static constexpr int NPW   = BN / 4;
    static constexpr int OCC   = (BN == 128) ? 2 : 1;
};

template<int EPI, int BN>
__global__ __launch_bounds__(256, GCfg<BN>::OCC)
void gemm_mma(const f16* __restrict__ Ah, const f16* __restrict__ Bh,
              const float* __restrict__ bias, const float* __restrict__ res,
              float* __restrict__ outf, f16* __restrict__ outh,
              int K, int Nfull) {
    using C = GCfg<BN>;
    extern __shared__ char dsm[];
    uint32_t tiles = smem_u32(dsm);

    int tid = threadIdx.x;
    int wid = tid >> 5;
    int lane = tid & 31;
    int warp_m = wid & 1;
    int warp_n = wid >> 1;
    int m0 = blockIdx.y * 128;
    int n0 = blockIdx.x * BN;
    int nt = K >> 5;

    int aRow  = lane & 15;
    int aColB = (lane >> 4) << 4;
    int bRow  = (lane & 7) + ((lane & 16) >> 1);
    int bColB = (lane & 8) << 1;

    float acc[4][C::NF][4];
    #pragma unroll
    for (int mt = 0; mt < 4; mt++)
        #pragma unroll
        for (int ntl = 0; ntl < C::NF; ntl++)
            #pragma unroll
            for (int r = 0; r < 4; r++) acc[mt][ntl][r] = 0.f;

    auto load_stage = [&](int kt, int st) {
        uint32_t sb = tiles + st * C::STAGE;
        int k0 = kt << 5;
        #pragma unroll
        for (int i = 0; i < 2; i++) {
            int id = tid + (i << 8);
            int r = id >> 2, c = id & 3;
            size_t go = (size_t)(m0 + r) * K + k0 + (c << 3);
            cp16(sb + C::A_OFF + r * ROWB + (c << 4), Ah + go);
        }
        #pragma unroll
        for (int i = 0; i < BN / 64; i++) {
            int id = tid + (i << 8);
            int r = id >> 2, c = id & 3;
            size_t go = (size_t)(n0 + r) * K + k0 + (c << 3);
            cp16(sb + C::B_OFF + r * ROWB + (c << 4), Bh + go);
        }
        asm volatile("cp.async.commit_group;" ::: "memory");
    };

    load_stage(0, 0);
    load_stage(1, 1);

    uint32_t aH[16], bH[2 * C::NF];

    for (int kt = 0; kt < nt; kt++) {
        int cur = kt & 3;
        if (kt + 2 < nt) {
            load_stage(kt + 2, (kt + 2) & 3);
            asm volatile("cp.async.wait_group 2;" ::: "memory");
        } else if (kt + 1 < nt) {
            asm volatile("cp.async.wait_group 1;" ::: "memory");
        } else {
            asm volatile("cp.async.wait_group 0;" ::: "memory");
        }
        __syncthreads();

        uint32_t sb = tiles + cur * C::STAGE;
        uint32_t aBase = sb + (warp_m * 64 + aRow) * ROWB + aColB;
        uint32_t bBase = sb + C::B_OFF + (warp_n * C::NPW + bRow) * ROWB + bColB;

        #pragma unroll
        for (int ks = 0; ks < 2; ks++) {
            uint32_t kb = ks << 5;
            #pragma unroll
            for (int mt = 0; mt < 4; mt++)
                ldsm4(&aH[4 * mt], aBase + mt * (16 * ROWB) + kb);
            #pragma unroll
            for (int p = 0; p < BN / 64; p++)
                ldsm4(&bH[4 * p], bBase + p * (16 * ROWB) + kb);
            #pragma unroll
            for (int mt = 0; mt < 4; mt++)
                #pragma unroll
                for (int ntl = 0; ntl < C::NF; ntl++)
                    mma16816(acc[mt][ntl], &aH[4 * mt], &bH[2 * ntl]);
        }
    }

    int m_base = m0 + warp_m * 64 + (lane >> 2);
    int n_base = n0 + warp_n * C::NPW + ((lane & 3) << 1);
    #pragma unroll
    for (int mt = 0; mt < 4; mt++) {
        #pragma unroll
        for (int ntl = 0; ntl < C::NF; ntl++) {
            int n = n_base + ntl * 8;
            float b0 = bias[n], b1 = bias[n + 1];
            #pragma unroll
            for (int rr = 0; rr < 2; rr++) {
                int m = m_base + mt * 16 + rr * 8;
                size_t ob = (size_t)m * Nfull + n;
                float v0 = acc[mt][ntl][2 * rr]     + b0;
                float v1 = acc[mt][ntl][2 * rr + 1] + b1;
                if (EPI == 0) {
                    *(__half2*)(outh + ob) =
                        __halves2half2(__float2half_rn(v0), __float2half_rn(v1));
                } else if (EPI == 2) {
                    float2 rv = *(const float2*)(res + ob);
                    *(float2*)(outf + ob) = make_float2(v0 + rv.x, v1 + rv.y);
                } else {
                    float g0 = gelu_exact(v0), g1 = gelu_exact(v1);
                    *(__half2*)(outh + ob) =
                        __halves2half2(__float2half_rn(g0), __float2half_rn(g1));
                }
            }
        }
    }
}

// ---------------- tensor-core flash attention (R13 config: single buffer) ----------
#define QSTR 72
#define VSTR 40

__global__ __launch_bounds__(128)
void attn_kernel(const f16* __restrict__ qkv, const char* __restrict__ mask,
                 f16* __restrict__ outh) {
    __shared__ f16 sQ[64 * QSTR];
    __shared__ f16 sK[32 * QSTR];
    __shared__ f16 sV[64 * VSTR];    // V^T: [dim][key]
    __shared__ char Ms[32];

    int qt = blockIdx.x, h = blockIdx.y, b = blockIdx.z;
    int tid = threadIdx.x;
    int wid = tid >> 5, lane = tid & 31;
    int grp = lane >> 2, qd = lane & 3;

    {
        int row = tid >> 1;
        int c0 = (tid & 1) * 32;
        const f16* g = qkv + ((size_t)(b * T_ + qt * 64 + row)) * D3_ + h * DH_ + c0;
        __half2 sc = __half2half2(__float2half(0.125f));
        #pragma unroll
        for (int u = 0; u < 16; u++) {
            __half2 v = *(const __half2*)(g + 2 * u);
            *(__half2*)&sQ[row * QSTR + c0 + 2 * u] = __hmul2(v, sc);
        }
    }

    float O[8][4];
    #pragma unroll
    for (int nf = 0; nf < 8; nf++)
        #pragma unroll
        for (int r = 0; r < 4; r++) O[nf][r] = 0.f;
    float m_a = -INFINITY, m_b = -INFINITY, l_a = 0.f, l_b = 0.f;

    uint32_t aAddr = smem_u32(sQ) + (wid * 16 + (lane & 15)) * (QSTR * 2) + ((lane >> 4) << 4);
    int bRow  = (lane & 7) + ((lane & 16) >> 1);
    int bColB = (lane & 8) << 1;
    uint32_t kAddr = smem_u32(sK) + bRow * (QSTR * 2) + bColB;
    uint32_t vAddr = smem_u32(sV) + bRow * (VSTR * 2) + bColB;

    int q_a = qt * 64 + wid * 16 + grp;
    int q_b = q_a + 8;

    int ktmax = (qt + 1) * 2;
    for (int kt = 0; kt < ktmax; kt++) {
        __syncthreads();
        {
            int j  = tid >> 2;
            int d0 = (tid & 3) * 16;
            const f16* gk = qkv + ((size_t)(b * T_ + kt * 32 + j)) * D3_ + D_ + h * DH_ + d0;
            const f16* gv = gk + D_;
            #pragma unroll
            for (int u = 0; u < 2; u++)
                *(uint4*)&sK[j * QSTR + d0 + u * 8] = *(const uint4*)(gk + u * 8);
            #pragma unroll
            for (int u = 0; u < 8; u++) {
                __half2 v = *(const __half2*)(gv + 2 * u);
                int d = d0 + 2 * u;
                sV[(d + 0) * VSTR + j] = __low2half(v);
                sV[(d + 1) * VSTR + j] = __high2half(v);
            }
            if (tid < 32) Ms[tid] = mask[b * T_ + kt * 32 + tid];
        }
        __syncthreads();

        float S[4][4];
        #pragma unroll
        for (int f = 0; f < 4; f++)
            #pragma unroll
            for (int r = 0; r < 4; r++) S[f][r] = 0.f;
        #pragma unroll
        for (int kc = 0; kc < 4; kc++) {
            uint32_t q[4], kf[8];
            ldsm4(q, aAddr + kc * 32);
            ldsm4(&kf[0], kAddr + kc * 32);
            ldsm4(&kf[4], kAddr + 16 * (QSTR * 2) + kc * 32);
            #pragma unroll
            for (int f = 0; f < 4; f++)
                mma16816(S[f], q, &kf[2 * f]);
        }

        float mt_a = -INFINITY, mt_b = -INFINITY;
        #pragma unroll
        for (int f = 0; f < 4; f++) {
            int ci = f * 8 + qd * 2;
            int gk0 = kt * 32 + ci, gk1 = gk0 + 1;
            bool ok0 = Ms[ci] != 0, ok1 = Ms[ci + 1] != 0;
            S[f][0] = (ok0 && gk0 <= q_a) ? S[f][0] : -INFINITY;
            S[f][1] = (ok1 && gk1 <= q_a) ? S[f][1] : -INFINITY;
            S[f][2] = (ok0 && gk0 <= q_b) ? S[f][2] : -INFINITY;
            S[f][3] = (ok1 && gk1 <= q_b) ? S[f][3] : -INFINITY;
            mt_a = fmaxf(mt_a, fmaxf(S[f][0], S[f][1]));
            mt_b = fmaxf(mt_b, fmaxf(S[f][2], S[f][3]));
        }
        mt_a = fmaxf(mt_a, __shfl_xor_sync(0xffffffffu, mt_a, 1));
        mt_a = fmaxf(mt_a, __shfl_xor_sync(0xffffffffu, mt_a, 2));
        mt_b = fmaxf(mt_b, __shfl_xor_sync(0xffffffffu, mt_b, 1));
        mt_b = fmaxf(mt_b, __shfl_xor_sync(0xffffffffu, mt_b, 2));
        float mn_a = fmaxf(m_a, mt_a), mn_b = fmaxf(m_b, mt_b);
        float al_a, al_b, ps_a = 0.f, ps_b = 0.f;
        if (mn_a == -INFINITY) {
            al_a = 1.f;
            #pragma unroll
            for (int f = 0; f < 4; f++) { S[f][0] = 0.f; S[f][1] = 0.f; }
        } else {
            al_a = expf(m_a - mn_a);
            #pragma unroll
            for (int f = 0; f < 4; f++) {
                S[f][0] = expf(S[f][0] - mn_a);
                S[f][1] = expf(S[f][1] - mn_a);
                ps_a += S[f][0] + S[f][1];
            }
        }
        if (mn_b == -INFINITY) {
            al_b = 1.f;
            #pragma unroll
            for (int f = 0; f < 4; f++) { S[f][2] = 0.f; S[f][3] = 0.f; }
        } else {
            al_b = expf(m_b - mn_b);
            #pragma unroll
            for (int f = 0; f < 4; f++) {
                S[f][2] = expf(S[f][2] - mn_b);
                S[f][3] = expf(S[f][3] - mn_b);
                ps_b += S[f][2] + S[f][3];
            }
        }
        ps_a += __shfl_xor_sync(0xffffffffu, ps_a, 1);
        ps_a += __shfl_xor_sync(0xffffffffu, ps_a, 2);
        ps_b += __shfl_xor_sync(0xffffffffu, ps_b, 1);
        ps_b += __shfl_xor_sync(0xffffffffu, ps_b, 2);
        l_a = l_a * al_a + ps_a;
        l_b = l_b * al_b + ps_b;
        m_a = mn_a; m_b = mn_b;
        #pragma unroll
        for (int nf = 0; nf < 8; nf++) {
            O[nf][0] *= al_a; O[nf][1] *= al_a;
            O[nf][2] *= al_b; O[nf][3] *= al_b;
        }

        #pragma unroll
        for (int kc = 0; kc < 2; kc++) {
            int f0 = 2 * kc, f1 = 2 * kc + 1;
            uint32_t pa[4];
            pa[0] = pack_h2(__float2half_rn(S[f0][0]), __float2half_rn(S[f0][1]));
            pa[1] = pack_h2(__float2half_rn(S[f0][2]), __float2half_rn(S[f0][3]));
            pa[2] = pack_h2(__float2half_rn(S[f1][0]), __float2half_rn(S[f1][1]));
            pa[3] = pack_h2(__float2half_rn(S[f1][2]), __float2half_rn(S[f1][3]));
            uint32_t vf[16];
            #pragma unroll
            for (int p4 = 0; p4 < 4; p4++)
                ldsm4(&vf[4 * p4], vAddr + p4 * 16 * (VSTR * 2) + kc * 32);
            #pragma unroll
            for (int nf = 0; nf < 8; nf++)
                mma16816(O[nf], pa, &vf[2 * nf]);
        }
    }

    float rl_a = (l_a > 0.f) ? (1.f / l_a) : 0.f;
    float rl_b = (l_b > 0.f) ? (1.f / l_b) : 0.f;
    size_t rowA = (size_t)(b * T_) + qt * 64 + wid * 16 + grp;
    size_t rowB = rowA + 8;
    #pragma unroll
    for (int nf = 0; nf < 8; nf++) {
        int col = h * DH_ + nf * 8 + qd * 2;
        *(__half2*)(outh + rowA * D_ + col) = __halves2half2(
            __float2half_rn(O[nf][0] * rl_a), __float2half_rn(O[nf][1] * rl_a));
        *(__half2*)(outh + rowB * D_ + col) = __halves2half2(
            __float2half_rn(O[nf][2] * rl_b), __float2half_rn(O[nf][3] * rl_b));
    }
}

// ---------------- head ----------------
__global__ void head_kernel(const float* __restrict__ xn, const int* __restrict__ lastidx,
                            const float* __restrict__ hw, const float* __restrict__ hb,
                            float* __restrict__ out) {
    int b = blockIdx.x;
    int w = threadIdx.x >> 5;
    int lane = threadIdx.x & 31;
    const float* h = xn + ((size_t)(b * T_ + lastidx[b])) * D_;
    float s = 0.f;
    for (int d = lane; d < D_; d += 32) s += h[d] * hw[d * 9 + w];
    #pragma unroll
    for (int o = 16; o; o >>= 1) s += __shfl_down_sync(0xffffffffu, s, o);
    if (lane == 0) out[b * 9 + w] = s + hb[w];
}

// ---------------- orchestration ----------------
extern "C" void kernel_launch(void* const* d_in, const int* in_sizes, int n_in,
                              void* d_out, int out_size) {
    const int*   cards   = (const int*)  d_in[0];
    const int*   players = (const int*)  d_in[1];
    const int*   deck    = (const int*)  d_in[2];
    const int*   opp     = (const int*)  d_in[3];
    const float* tok     = (const float*)d_in[4];
    const float* pemb    = (const float*)d_in[5];
    const float* pos     = (const float*)d_in[6];
    const float* ln1s = (const float*)d_in[9];
    const float* ln1b = (const float*)d_in[10];
    const float* qkvw = (const float*)d_in[11];
    const float* qkvb = (const float*)d_in[12];
    const float* projw = (const float*)d_in[13];
    const float* projb = (const float*)d_in[14];
    const float* ln2s = (const float*)d_in[15];
    const float* ln2b = (const float*)d_in[16];
    const float* fc1w = (const float*)d_in[17];
    const float* fc1b = (const float*)d_in[18];
    const float* fc2w = (const float*)d_in[19];
    const float* fc2b = (const float*)d_in[20];
    const float* lnfs = (const float*)d_in[21];
    const float* lnfb = (const float*)d_in[22];
    const float* headw = (const float*)d_in[23];
    const float* headb = (const float*)d_in[24];

    float *x, *xn, *dm;
    f16 *qkv, *xh, *yh, *hh;
    f16 *qT, *pT, *f1T, *f2T;
    char* mask; int* lastidx;
    cudaGetSymbolAddress((void**)&x,    g_x);
    cudaGetSymbolAddress((void**)&xn,   g_xn);
    cudaGetSymbolAddress((void**)&qkv,  g_qkv);
    cudaGetSymbolAddress((void**)&dm,   g_dm);
    cudaGetSymbolAddress((void**)&xh,   g_xh);
    cudaGetSymbolAddress((void**)&yh,   g_yh);
    cudaGetSymbolAddress((void**)&hh,   g_hh);
    cudaGetSymbolAddress((void**)&qT,   g_qkvT);
    cudaGetSymbolAddress((void**)&pT,   g_projT);
    cudaGetSymbolAddress((void**)&f1T,  g_fc1T);
    cudaGetSymbolAddress((void**)&f2T,  g_fc2T);
    cudaGetSymbolAddress((void**)&mask, g_mask);
    cudaGetSymbolAddress((void**)&lastidx, g_lastidx);

    cudaFuncSetAttribute((const void*)gemm_mma<0, 128>,
                         cudaFuncAttributeMaxDynamicSharedMemorySize, GCfg<128>::SMEM);
    cudaFuncSetAttribute((const void*)gemm_mma<1, 128>,
                         cudaFuncAttributeMaxDynamicSharedMemorySize, GCfg<128>::SMEM);
    cudaFuncSetAttribute((const void*)gemm_mma<2, 128>,
                         cudaFuncAttributeMaxDynamicSharedMemorySize, GCfg<128>::SMEM);

    dim3 tb(32, 8);
    transpose_all<<<TFC2, tb>>>(qkvw, projw, fc1w, fc2w, qT, pT, f1T, f2T);
    mask_kernel<<<B_, T_>>>(cards, mask, lastidx);
    deckmean_kernel<<<B_, D_>>>(deck, opp, tok, dm);
    embed_kernel<<<BT_, 256>>>(cards, players, tok, pemb, pos, dm, x);

    for (int i = 0; i < L_; i++) {
        ln_kernel<true><<<BT_, 256>>>(x, ln1s + i * D_, ln1b + i * D_, nullptr, xh);
        gemm_mma<0, 128><<<dim3(D3_ / 128, BT_ / 128), 256, GCfg<128>::SMEM>>>(
            xh, qT + (size_t)i * D3_ * D_,
            qkvb + i * D3_, nullptr, nullptr, qkv, D_, D3_);
        attn_kernel<<<dim3(T_ / 64, NH_, B_), 128>>>(qkv, mask, yh);
        gemm_mma<2, 128><<<dim3(D_ / 128, BT_ / 128), 256, GCfg<128>::SMEM>>>(
            yh, pT + (size_t)i * D_ * D_,
            projb + i * D_, x, x, nullptr, D_, D_);
        ln_kernel<true><<<BT_, 256>>>(x, ln2s + i * D_, ln2b + i * D_, nullptr, xh);
        gemm_mma<1, 128><<<dim3(D4_ / 128, BT_ / 128), 256, GCfg<128>::SMEM>>>(
            xh, f1T + (size_t)i * D4_ * D_,
            fc1b + i * D4_, nullptr, nullptr, hh, D_, D4_);
        gemm_mma<2, 128><<<dim3(D_ / 128, BT_ / 128), 256, GCfg<128>::SMEM>>>(
            hh, f2T + (size_t)i * D_ * D4_,
            fc2b + i * D_, x, x, nullptr, D4_, D_);
    }

    ln_kernel<false><<<BT_, 256>>>(x, lnfs, lnfb, xn, nullptr);
    head_kernel<<<B_, 288>>>(xn, lastidx, headw, headb, (float*)d_out);
}